// round 11
// baseline (speedup 1.0000x reference)
#include <cuda_runtime.h>
#include <cuda_bf16.h>
#include <cuda_fp16.h>
#include <cstdint>

#define NMAX 50000

extern __shared__ __align__(1024) char smem_raw[];

// ---------------- scratch ----------------------------------------------------
__device__ float g_agg[NMAX * 128];
__device__ __align__(16) unsigned short g_P1h[NMAX * 128];  // fp16: h@W_d + eb1
__device__ __align__(16) unsigned short g_P2h[NMAX * 128];  // fp16: h@W_s
__device__ float g_delta[NMAX * 3];
__device__ float g_deg[NMAX];
__device__ int   g_is64;
__device__ int   g_skip_coord;
// fp16 weight images, row-major [out n][in k]
__device__ __align__(16) unsigned short g_Bh[16384];    // ew2^T
__device__ __align__(16) unsigned short g_Bd[16384];    // ew1[0:128]^T
__device__ __align__(16) unsigned short g_Bs[16384];    // ew1[128:256]^T
__device__ __align__(16) unsigned short g_Bn1[32768];   // nw1^T [128][256]
__device__ __align__(16) unsigned short g_Bn2[16384];   // nw2^T [128][128]

__device__ __forceinline__ float silu_f(float v) { return v / (1.f + __expf(-v)); }

// ---------------- ptx helpers ----------------------------------------------
#define LDSM_X4(r, addr) \
    asm volatile("ldmatrix.sync.aligned.m8n8.x4.shared.b16 {%0,%1,%2,%3}, [%4];" \
        : "=r"((r)[0]), "=r"((r)[1]), "=r"((r)[2]), "=r"((r)[3]) : "r"(addr))

// fp16-accumulate HMMA: D/C are 2 packed half2 regs.
__device__ __forceinline__ void mma16816h(uint32_t* d, const uint32_t* a, const uint32_t* b) {
    asm volatile("mma.sync.aligned.m16n8k16.row.col.f16.f16.f16.f16 "
        "{%0,%1}, {%2,%3,%4,%5}, {%6,%7}, {%0,%1};"
        : "+r"(d[0]), "+r"(d[1])
        : "r"(a[0]), "r"(a[1]), "r"(a[2]), "r"(a[3]), "r"(b[0]), "r"(b[1]));
}

__device__ __forceinline__ void red_add_v4(float* p, float a, float b, float c, float d) {
    asm volatile("red.global.add.v4.f32 [%0], {%1, %2, %3, %4};"
        :: "l"(p), "f"(a), "f"(b), "f"(c), "f"(d) : "memory");
}

__device__ __forceinline__ float2 h2f2(uint32_t u) {
    __half2 h = *(__half2*)&u;
    return __half22float2(h);
}

#define APITCH  136
#define AROWB   272
#define TILE_B  (128 * AROWB)        // 34816 bytes per 128-row fp16 tile

// ---------------- probes -----------------------------------------------------
__global__ void detect_kernel(const unsigned int* __restrict__ w,
                              const float* __restrict__ cw2,
                              const float* __restrict__ cb2) {
    if (threadIdx.x == 0) {
        int all0 = 1;
#pragma unroll
        for (int i = 1; i < 64; i += 2) all0 &= (w[i] == 0u);
        g_is64 = all0;
        int z = (cb2[0] == 0.f);
        for (int i = 0; i < 64; i++) z &= (cw2[i] == 0.f);
        g_skip_coord = z;
    }
}

__global__ void zero_kernel(int n) {
    int i = blockIdx.x * blockDim.x + threadIdx.x;
    if (i < n * 128) g_agg[i] = 0.f;
    if (i < n * 3)   g_delta[i] = 0.f;
    if (i < n)       g_deg[i] = 0.f;
}

// build all fp16 weight images
__global__ void build_b_kernel(const float* __restrict__ ew2,
                               const float* __restrict__ ew1,
                               const float* __restrict__ nw1,
                               const float* __restrict__ nw2) {
    int idx = blockIdx.x * 256 + threadIdx.x;   // 0..32767
    if (idx < 16384) {
        int j = idx >> 7, k = idx & 127;
        g_Bh[j * 128 + k] = __half_as_ushort(__float2half_rn(ew2[k * 128 + j]));
        g_Bd[j * 128 + k] = __half_as_ushort(__float2half_rn(ew1[k * 128 + j]));
        g_Bs[j * 128 + k] = __half_as_ushort(__float2half_rn(ew1[(128 + k) * 128 + j]));
        g_Bn2[j * 128 + k] = __half_as_ushort(__float2half_rn(nw2[k * 128 + j]));
    }
    {
        int j = idx >> 8, k = idx & 255;        // [128][256]
        g_Bn1[j * 256 + k] = __half_as_ushort(__float2half_rn(nw1[k * 128 + j]));
    }
}

// ---------------- HMMA proj kernel: P1h, P2h --------------------------------
#define PK_EB1  0
#define PK_A    1024
#define PK_BD   (PK_A + TILE_B)
#define PK_BS   (PK_BD + TILE_B)
#define PROJ_SMEM_BYTES (PK_BS + TILE_B)   // 105472

__global__ __launch_bounds__(512, 2) void proj_hmma(
    const float* __restrict__ h, const float* __restrict__ eb1, int N)
{
    char* smem = smem_raw;
    const uint32_t sb = (uint32_t)__cvta_generic_to_shared(smem);
    float* s_eb1 = (float*)(smem + PK_EB1);
    const int tid = threadIdx.x, wid = tid >> 5, lane = tid & 31;
    const int n0 = blockIdx.x * 128;

    if (tid < 32) *(float4*)(s_eb1 + tid * 4) = __ldg((const float4*)eb1 + tid);
    for (int i = tid; i < 128 * 16; i += 512) {
        int rw = i >> 4, c = i & 15;
        *(uint4*)(smem + PK_BD + rw * AROWB + c * 16) = ((const uint4*)g_Bd)[rw * 16 + c];
        *(uint4*)(smem + PK_BS + rw * AROWB + c * 16) = ((const uint4*)g_Bs)[rw * 16 + c];
    }
#pragma unroll
    for (int it = 0; it < 8; it++) {
        int row = wid * 8 + it;
        int n = n0 + row;
        float4 v = make_float4(0.f, 0.f, 0.f, 0.f);
        if (n < N) v = __ldg((const float4*)h + (size_t)n * 32 + lane);
        __half2 h01 = __floats2half2_rn(v.x, v.y);
        __half2 h23 = __floats2half2_rn(v.z, v.w);
        uint2 u; u.x = *(uint32_t*)&h01; u.y = *(uint32_t*)&h23;
        *(uint2*)(smem + PK_A + row * AROWB + lane * 8) = u;
    }
    __syncthreads();

    const int mw = wid & 7, nw = wid >> 3;   // 8 M-warps x 2 N-warps
    const int mi = lane >> 3, r = lane & 7;
    const uint32_t aBase = sb + PK_A
        + (uint32_t)((mw * 16 + (mi & 1) * 8 + r) * APITCH + (mi >> 1) * 8) * 2u;
    const uint32_t bBase = sb + PK_BD
        + (uint32_t)((nw * 64 + (mi >> 1) * 8 + r) * APITCH + (mi & 1) * 8) * 2u;
    const int gid = lane >> 2, tig = lane & 3;

    uint32_t c[8][2];
#pragma unroll
    for (int pass = 0; pass < 2; pass++) {
#pragma unroll
        for (int nt = 0; nt < 8; nt++) { c[nt][0] = 0u; c[nt][1] = 0u; }
        uint32_t bb = bBase + pass * (PK_BS - PK_BD);
#pragma unroll
        for (int ks = 0; ks < 8; ks++) {
            uint32_t af[4];
            LDSM_X4(af, aBase + ks * 32);
            uint32_t kb = bb + ks * 32;
#pragma unroll
            for (int np = 0; np < 4; np++) {
                uint32_t bf[4];
                LDSM_X4(bf, kb);
                mma16816h(c[2*np],   af, bf + 0);
                mma16816h(c[2*np+1], af, bf + 2);
                kb += 16 * AROWB;
            }
        }
        unsigned short* dst = pass == 0 ? g_P1h : g_P2h;
        int rA = mw * 16 + gid;
        int nA = n0 + rA, nB = nA + 8;
#pragma unroll
        for (int nt = 0; nt < 8; nt++) {
            int col = nw * 64 + nt * 8 + tig * 2;
            float b0 = pass == 0 ? s_eb1[col] : 0.f;
            float b1 = pass == 0 ? s_eb1[col + 1] : 0.f;
            float2 vA = h2f2(c[nt][0]);
            float2 vB = h2f2(c[nt][1]);
            if (nA < N)
                *(__half2*)(dst + (size_t)nA * 128 + col) =
                    __floats2half2_rn(vA.x + b0, vA.y + b1);
            if (nB < N)
                *(__half2*)(dst + (size_t)nB * 128 + col) =
                    __floats2half2_rn(vB.x + b0, vB.y + b1);
        }
    }
}

// ---------------- HMMA edge kernel: 256 edges/block --------------------------
#define EK_DST   0                     // int[256]
#define EK_SRC   1024                  // int[256]
#define EK_DSQ   2048                  // float[256]
#define EK_REL   3072                  // float[256][3]
#define EK_EA    6144                  // half[256][4]
#define EK_TAIL  8192                  // float[5][128]
#define EK_EB2   10752                 // float[128]
#define EK_A     11264                 // 256 x 272 = 69632
#define EK_B     (EK_A + 256 * AROWB)  // 80896
#define EK_MSG   EK_A                  // fp32 [128][128] half-pass staging
#define EDGE_SMEM_BYTES (EK_B + TILE_B)   // 115712

__global__ __launch_bounds__(512, 2) void edge_tc_kernel(
    const float* __restrict__ x,
    const void*  __restrict__ eidx, const float* __restrict__ eattr,
    const float* __restrict__ ew1, const float* __restrict__ eb2,
    const float* __restrict__ cw1, const float* __restrict__ cb1,
    const float* __restrict__ cw2, const float* __restrict__ cb2,
    int E)
{
    char* smem = smem_raw;
    const uint32_t sb = (uint32_t)__cvta_generic_to_shared(smem);
    int*    s_dst  = (int*)(smem + EK_DST);
    int*    s_src  = (int*)(smem + EK_SRC);
    float*  s_dsq  = (float*)(smem + EK_DSQ);
    float*  s_rel  = (float*)(smem + EK_REL);
    __half* s_ea   = (__half*)(smem + EK_EA);
    float*  s_tail = (float*)(smem + EK_TAIL);
    float*  s_eb2  = (float*)(smem + EK_EB2);

    const int tid  = threadIdx.x;
    const int wid  = tid >> 5;
    const int lane = tid & 31;
    const int e0   = blockIdx.x * 256;

    if (tid < 256) {
        int ge = e0 + tid;
        int dI = -1, sI = 0;
        float rx = 0.f, ry = 0.f, rz = 0.f, dsq = 1e-8f;
        float4 ea = make_float4(0.f, 0.f, 0.f, 0.f);
        if (ge < E) {
            if (g_is64) {
                const long long* p = (const long long*)eidx;
                sI = (int)p[ge]; dI = (int)p[E + ge];
            } else {
                const int* p = (const int*)eidx;
                sI = p[ge]; dI = p[E + ge];
            }
            const float* xd = x + (size_t)dI * 3;
            const float* xs = x + (size_t)sI * 3;
            rx = xd[0] - xs[0]; ry = xd[1] - xs[1]; rz = xd[2] - xs[2];
            dsq = fmaxf(rx * rx + ry * ry + rz * rz, 1e-8f);
            ea = ((const float4*)eattr)[ge];
        }
        s_dst[tid] = dI; s_src[tid] = sI;
        s_rel[tid * 3 + 0] = rx; s_rel[tid * 3 + 1] = ry; s_rel[tid * 3 + 2] = rz;
        s_dsq[tid] = dsq;
        __half2 e01 = __floats2half2_rn(ea.x, ea.y);
        __half2 e23 = __floats2half2_rn(ea.z, ea.w);
        uint2 u; u.x = *(uint32_t*)&e01; u.y = *(uint32_t*)&e23;
        *(uint2*)(s_ea + tid * 4) = u;
    }
    if (tid >= 256 && tid < 416) {
        int t = tid - 256;
        int r = t >> 5, c = t & 31;
        *(float4*)(s_tail + r * 128 + c * 4) =
            __ldg((const float4*)(ew1 + (256 + r) * 128) + c);
    }
    if (tid >= 416 && tid < 448)
        *(float4*)(s_eb2 + (tid - 416) * 4) = __ldg((const float4*)eb2 + (tid - 416));
    for (int i = tid; i < 128 * 16; i += 512) {
        int rw = i >> 4, c = i & 15;
        *(uint4*)(smem + EK_B + rw * AROWB + c * 16) = ((const uint4*)g_Bh)[rw * 16 + c];
    }
    __syncthreads();

    // ---- gather fp16 P1/P2 + tail + silu -> fp16 A tile (16 edges/warp) ----
#pragma unroll 4
    for (int it = 0; it < 16; it++) {
        int e  = wid * 16 + it;
        int dI = s_dst[e];
        float4 v = make_float4(0.f, 0.f, 0.f, 0.f);
        if (dI >= 0) {
            uint2 ua = *(const uint2*)(g_P1h + (size_t)dI * 128 + lane * 4);
            uint2 ub = *(const uint2*)(g_P2h + (size_t)s_src[e] * 128 + lane * 4);
            __half2 a01 = *(__half2*)&ua.x, a23 = *(__half2*)&ua.y;
            __half2 b01 = *(__half2*)&ub.x, b23 = *(__half2*)&ub.y;
            float ds = s_dsq[e];
            uint2 ue = *(const uint2*)(s_ea + e * 4);
            float2 e01 = h2f2(ue.x), e23 = h2f2(ue.y);
            float4 ea = make_float4(e01.x, e01.y, e23.x, e23.y);
            float4 wd = *(const float4*)(s_tail + 0 * 128 + lane * 4);
            float4 a0 = *(const float4*)(s_tail + 1 * 128 + lane * 4);
            float4 a1 = *(const float4*)(s_tail + 2 * 128 + lane * 4);
            float4 a2 = *(const float4*)(s_tail + 3 * 128 + lane * 4);
            float4 a3 = *(const float4*)(s_tail + 4 * 128 + lane * 4);
            v.x = __low2float(a01)  + __low2float(b01)
                + fmaf(ds,wd.x,fmaf(ea.x,a0.x,fmaf(ea.y,a1.x,fmaf(ea.z,a2.x,ea.w*a3.x))));
            v.y = __high2float(a01) + __high2float(b01)
                + fmaf(ds,wd.y,fmaf(ea.x,a0.y,fmaf(ea.y,a1.y,fmaf(ea.z,a2.y,ea.w*a3.y))));
            v.z = __low2float(a23)  + __low2float(b23)
                + fmaf(ds,wd.z,fmaf(ea.x,a0.z,fmaf(ea.y,a1.z,fmaf(ea.z,a2.z,ea.w*a3.z))));
            v.w = __high2float(a23) + __high2float(b23)
                + fmaf(ds,wd.w,fmaf(ea.x,a0.w,fmaf(ea.y,a1.w,fmaf(ea.z,a2.w,ea.w*a3.w))));
            v.x = silu_f(v.x); v.y = silu_f(v.y); v.z = silu_f(v.z); v.w = silu_f(v.w);
        }
        __half2 h01 = __floats2half2_rn(v.x, v.y);
        __half2 h23 = __floats2half2_rn(v.z, v.w);
        uint2 u; u.x = *(uint32_t*)&h01; u.y = *(uint32_t*)&h23;
        *(uint2*)(smem + EK_A + e * AROWB + lane * 8) = u;
    }
    __syncthreads();

    // ---- fp16 HMMA (f16 accum), each warp D[32 x 64] ----
    const int mw = wid & 7;            // 8 M-warps x 32 rows = 256
    const int nw = wid >> 3;           // 2 N-warps x 64 cols
    uint32_t c[2][8][2];
#pragma unroll
    for (int mt = 0; mt < 2; mt++)
#pragma unroll
        for (int nt = 0; nt < 8; nt++) { c[mt][nt][0] = 0u; c[mt][nt][1] = 0u; }
    {
        const int mi = lane >> 3, r = lane & 7;
        uint32_t aBase0 = sb + EK_A
            + (uint32_t)((mw * 32 + (mi & 1) * 8 + r) * APITCH + (mi >> 1) * 8) * 2u;
        uint32_t aBase1 = aBase0 + 16 * AROWB;
        uint32_t bBase = sb + EK_B
            + (uint32_t)((nw * 64 + (mi >> 1) * 8 + r) * APITCH + (mi & 1) * 8) * 2u;
#pragma unroll
        for (int ks = 0; ks < 8; ks++) {
            uint32_t af0[4], af1[4];
            LDSM_X4(af0, aBase0 + ks * 32);
            LDSM_X4(af1, aBase1 + ks * 32);
            uint32_t kb = bBase + ks * 32;
#pragma unroll
            for (int np = 0; np < 4; np++) {
                uint32_t bf[4];
                LDSM_X4(bf, kb);
                mma16816h(c[0][2*np],   af0, bf + 0);
                mma16816h(c[0][2*np+1], af0, bf + 2);
                mma16816h(c[1][2*np],   af1, bf + 0);
                mma16816h(c[1][2*np+1], af1, bf + 2);
                kb += 16 * AROWB;
            }
        }
    }

    // ---- bias + silu; pair-shuffle v4 reductions into g_agg ----
    const int gid = lane >> 2, tig = lane & 3;
    const int skip = g_skip_coord;
#pragma unroll
    for (int mt = 0; mt < 2; mt++) {
        int rA = mw * 32 + mt * 16 + gid;
        int rB = rA + 8;
        int dA = s_dst[rA], dB = s_dst[rB];
#pragma unroll
        for (int nt = 0; nt < 8; nt++) {
            int col = nw * 64 + nt * 8 + tig * 2;
            float b0 = s_eb2[col], b1 = s_eb2[col + 1];
            float2 vA = h2f2(c[mt][nt][0]);
            float2 vB = h2f2(c[mt][nt][1]);
            float mA0 = silu_f(vA.x + b0), mA1 = silu_f(vA.y + b1);
            float mB0 = silu_f(vB.x + b0), mB1 = silu_f(vB.y + b1);
            float pA0 = __shfl_down_sync(0xffffffffu, mA0, 1);
            float pA1 = __shfl_down_sync(0xffffffffu, mA1, 1);
            float pB0 = __shfl_down_sync(0xffffffffu, mB0, 1);
            float pB1 = __shfl_down_sync(0xffffffffu, mB1, 1);
            if ((tig & 1) == 0) {
                if (dA >= 0)
                    red_add_v4(g_agg + (size_t)dA * 128 + col, mA0, mA1, pA0, pA1);
                if (dB >= 0)
                    red_add_v4(g_agg + (size_t)dB * 128 + col, mB0, mB1, pB0, pB1);
            }
        }
    }

    if (skip) return;

    // ---- fallback coord path: two half-passes of 128 rows ----
    for (int hf = 0; hf < 2; hf++) {
        __syncthreads();
        float* s_msg = (float*)(smem + EK_MSG);
        if ((mw >> 2) == hf) {
            int lm = mw & 3;   // local m-warp within half
#pragma unroll
            for (int mt = 0; mt < 2; mt++) {
                int rA = lm * 32 + mt * 16 + gid;   // local row in half
                int rB = rA + 8;
#pragma unroll
                for (int nt = 0; nt < 8; nt++) {
                    int col = nw * 64 + nt * 8 + tig * 2;
                    float b0 = s_eb2[col], b1 = s_eb2[col + 1];
                    float2 vA = h2f2(c[mt][nt][0]);
                    float2 vB = h2f2(c[mt][nt][1]);
                    *(float2*)(s_msg + rA * 128 + col) =
                        make_float2(silu_f(vA.x + b0), silu_f(vA.y + b1));
                    *(float2*)(s_msg + rB * 128 + col) =
                        make_float2(silu_f(vB.x + b0), silu_f(vB.y + b1));
                }
            }
        }
        __syncthreads();
        {
            const int jc = tid & 15;
            const int ec = tid >> 4;   // 32 groups x 4 local rows
            float4 acc3[4];
#pragma unroll
            for (int e = 0; e < 4; e++) acc3[e] = make_float4(0.f, 0.f, 0.f, 0.f);
            const float4* C1 = (const float4*)cw1;
            const float* sM = s_msg + ec * 4 * 128;
#pragma unroll 2
            for (int k4 = 0; k4 < 32; k4++) {
                const int kb = k4 * 4;
                float4 w0 = __ldg(C1 + (kb + 0) * 16 + jc);
                float4 w1 = __ldg(C1 + (kb + 1) * 16 + jc);
                float4 w2 = __ldg(C1 + (kb + 2) * 16 + jc);
                float4 w3 = __ldg(C1 + (kb + 3) * 16 + jc);
#pragma unroll
                for (int e = 0; e < 4; e++) {
                    float4 a = *(const float4*)(sM + e * 128 + kb);
                    acc3[e].x = fmaf(a.x,w0.x,fmaf(a.y,w1.x,fmaf(a.z,w2.x,fmaf(a.w,w3.x,acc3[e].x))));
                    acc3[e].y = fmaf(a.x,w0.y,fmaf(a.y,w1.y,fmaf(a.z,w2.y,fmaf(a.w,w3.y,acc3[e].y))));
                    acc3[e].z = fmaf(a.x,w0.z,fmaf(a.y,w1.z,fmaf(a.z,w2.z,fmaf(a.w,w3.z,acc3[e].z))));
                    acc3[e].w = fmaf(a.x,w0.w,fmaf(a.y,w1.w,fmaf(a.z,w2.w,fmaf(a.w,w3.w,acc3[e].w))));
                }
            }
            float4 bc = __ldg((const float4*)cb1 + jc);
            float4 c2 = __ldg((const float4*)cw2 + jc);
            float part[4];
#pragma unroll
            for (int e = 0; e < 4; e++) {
                float cx = silu_f(acc3[e].x + bc.x);
                float cy = silu_f(acc3[e].y + bc.y);
                float cz = silu_f(acc3[e].z + bc.z);
                float cw_ = silu_f(acc3[e].w + bc.w);
                part[e] = cx * c2.x + cy * c2.y + cz * c2.z + cw_ * c2.w;
            }
#pragma unroll
            for (int off = 8; off > 0; off >>= 1) {
#pragma unroll
                for (int e = 0; e < 4; e++)
                    part[e] += __shfl_xor_sync(0xffffffffu, part[e], off, 16);
            }
            if (jc == 0) {
                float cb2v = __ldg(cb2);
#pragma unroll
                for (int e = 0; e < 4; e++) {
                    int ee = hf * 128 + ec * 4 + e;   // block-local edge row
                    int dI = s_dst[ee];
                    if (dI >= 0) {
                        float wv = part[e] + cb2v;
                        float f = wv / (sqrtf(s_dsq[ee]) + 1.f);
                        atomicAdd(&g_delta[dI * 3 + 0], s_rel[ee * 3 + 0] * f);
                        atomicAdd(&g_delta[dI * 3 + 1], s_rel[ee * 3 + 1] * f);
                        atomicAdd(&g_delta[dI * 3 + 2], s_rel[ee * 3 + 2] * f);
                        atomicAdd(&g_deg[dI], 1.f);
                    }
                }
            }
        }
    }
}

// ---------------- HMMA node kernel ------------------------------------------
#define NK_NB1   0
#define NK_NB2   512
#define NK_LNG   1024
#define NK_LNB   1536
#define NK_A     2048
#define NK_B0    (NK_A + TILE_B)
#define NK_B1    (NK_B0 + TILE_B)
#define NK_O     2048
#define NODE_SMEM_BYTES (NK_B1 + TILE_B)   // 106496

__global__ __launch_bounds__(512, 2) void node_hmma(
    const float* __restrict__ h,
    const float* __restrict__ nb1, const float* __restrict__ nb2,
    const float* __restrict__ ln_g, const float* __restrict__ ln_b,
    float* __restrict__ out, int N)
{
    char* smem = smem_raw;
    const uint32_t sb = (uint32_t)__cvta_generic_to_shared(smem);
    float* s_nb1 = (float*)(smem + NK_NB1);
    float* s_nb2 = (float*)(smem + NK_NB2);
    float* s_lng = (float*)(smem + NK_LNG);
    float* s_lnb = (float*)(smem + NK_LNB);
    const int tid = threadIdx.x, wid = tid >> 5, lane = tid & 31;
    const int n0 = blockIdx.x * 128;

    if (tid < 32) {
        *(float4*)(s_nb1 + tid * 4) = __ldg((const float4*)nb1 + tid);
        *(float4*)(s_nb2 + tid * 4) = __ldg((const float4*)nb2 + tid);
        *(float4*)(s_lng + tid * 4) = __ldg((const float4*)ln_g + tid);
        *(float4*)(s_lnb + tid * 4) = __ldg((const float4*)ln_b + tid);
    }
    for (int i = tid; i < 128 * 16; i += 512) {
        int rw = i >> 4, c = i & 15;
        *(uint4*)(smem + NK_B0 + rw * AROWB + c * 16) = ((const uint4*)g_Bn1)[rw * 32 + c];
        *(uint4*)(smem + NK_B1 + rw * AROWB + c * 16) = ((const uint4*)g_Bn1)[rw * 32 + 16 + c];
    }
#pragma unroll
    for (int it = 0; it < 8; it++) {
        int row = wid * 8 + it;
        int n = n0 + row;
        float4 v = make_float4(0.f, 0.f, 0.f, 0.f);
        if (n < N) v = __ldg((const float4*)h + (size_t)n * 32 + lane);
        __half2 h01 = __floats2half2_rn(v.x, v.y);
        __half2 h23 = __floats2half2_rn(v.z, v.w);
        uint2 u; u.x = *(uint32_t*)&h01; u.y = *(uint32_t*)&h23;
        *(uint2*)(smem + NK_A + row * AROWB + lane * 8) = u;
    }
    __syncthreads();

    const int mw = wid & 7, nw = wid >> 3;
    const int mi = lane >> 3, r = lane & 7;
    const uint32_t aBase = sb + NK_A
        + (uint32_t)((mw * 16 + (mi & 1) * 8 + r) * APITCH + (mi >> 1) * 8) * 2u;
    const uint32_t bBase0 = sb + NK_B0
        + (uint32_t)((nw * 64 + (mi >> 1) * 8 + r) * APITCH + (mi & 1) * 8) * 2u;
    const int gid = lane >> 2, tig = lane & 3;

    uint32_t c[8][2];
#pragma unroll
    for (int nt = 0; nt < 8; nt++) { c[nt][0] = 0u; c[nt][1] = 0u; }

    // layer 1, k-half 0 (A = h fp16)
#pragma unroll
    for (int ks = 0; ks < 8; ks++) {
        uint32_t af[4];
        LDSM_X4(af, aBase + ks * 32);
        uint32_t kb = bBase0 + ks * 32;
#pragma unroll
        for (int np = 0; np < 4; np++) {
            uint32_t bf[4];
            LDSM_X4(bf, kb);
            mma16816h(c[2*np],   af, bf + 0);
            mma16816h(c[2*np+1], af, bf + 2);
            kb += 16 * AROWB;
        }
    }
    __syncthreads();
#pragma unroll
    for (int it = 0; it < 8; it++) {
        int row = wid * 8 + it;
        int n = n0 + row;
        float4 v = make_float4(0.f, 0.f, 0.f, 0.f);
        if (n < N) v = *((const float4*)g_agg + (size_t)n * 32 + lane);
        __half2 h01 = __floats2half2_rn(v.x, v.y);
        __half2 h23 = __floats2half2_rn(v.z, v.w);
        uint2 u; u.x = *(uint32_t*)&h01; u.y = *(uint32_t*)&h23;
        *(uint2*)(smem + NK_A + row * AROWB + lane * 8) = u;
    }
    __syncthreads();
    // layer 1, k-half 1 (A = agg)
#pragma unroll
    for (int ks = 0; ks < 8; ks++) {
        uint32_t af[4];
        LDSM_X4(af, aBase + ks * 32);
        uint32_t kb = bBase0 + (NK_B1 - NK_B0) + ks * 32;
#pragma unroll
        for (int np = 0; np < 4; np++) {
            uint32_t bf[4];
            LDSM_X4(bf, kb);
            mma16816h(c[2*np],   af, bf + 0);
            mma16816h(c[2*np+1], af, bf + 2);
            kb += 16 * AROWB;
        }
    }
    __syncthreads();
    // t1 = silu(c + nb1) -> fp16 into NK_A; Bn2 -> NK_B0
    {
        int rA = mw * 16 + gid;
        int rB = rA + 8;
#pragma unroll
        for (int nt = 0; nt < 8; nt++) {
            int col = nw * 64 + nt * 8 + tig * 2;
            float b0 = s_nb1[col], b1 = s_nb1[col + 1];
            float2 vA = h2f2(c[nt][0]);
            float2 vB = h2f2(c[nt][1]);
            *(__half2*)(smem + NK_A + rA * AROWB + col * 2) =
                __floats2half2_rn(silu_f(vA.x + b0), silu_f(vA.y + b1));
            *(__half2*)(smem + NK_A + rB * AROWB + col * 2) =
                __floats2half2_rn(silu_f(vB.x + b0), silu_f(vB.y + b1));
        }
    }
    for (int i = tid; i < 128 * 16; i += 512) {
        int rw = i >> 4, cc = i & 15;
        *(uint4*)(smem + NK_B0 + rw * AROWB + cc * 16) = ((const uint4*)g_Bn2)[rw * 16 + cc];
    }
    __syncthreads();

    // layer 2
#pragma unroll
    for (int nt = 0; nt < 8; nt++) { c[nt][0] = 0u; c[nt][1] = 0u; }
#pragma unroll
    for (int ks = 0; ks < 8; ks++) {
        uint32_t af[4];
        LDSM_X4(af, aBase + ks * 32);
        uint32_t kb = bBase0 + ks * 32;
#pragma unroll
        for (int np = 0; np < 4; np++) {
            uint32_t bf[4];
            LDSM_X4(bf, kb);
            mma16816h(c[2*np],   af, bf + 0);
            mma16816h(c[2*np+1], af, bf + 2);
            kb += 16 * AROWB;
        }
    }
    __syncthreads();
    // stage o = c + nb2 + h (residual) fp32 into NK_O (pitch 132)
    {
        float* s_o = (float*)(smem + NK_O);
        int rA = mw * 16 + gid;
        int rB = rA + 8;
        int nA = n0 + rA, nB = n0 + rB;
#pragma unroll
        for (int nt = 0; nt < 8; nt++) {
            int col = nw * 64 + nt * 8 + tig * 2;
            float b0 = s_nb2[col], b1 = s_nb2[col + 1];
            float2 hA = make_float2(0.f, 0.f), hB = make_float2(0.f, 0.f);
            if (nA < N) hA = *(const float2*)(h + (size_t)nA * 128 + col);
            if (nB < N) hB = *(const float2*)(h + (size_t)nB * 128 + col);
            float2 vA = h2f2(c[nt][0]);
            float2 vB = h2f2(c[nt][1]);
            *(float2*)(s_o + rA * 132 + col) =
                make_float2(vA.x + b0 + hA.x, vA.y + b1 + hA.y);
            *(float2*)(s_o + rB * 132 + col) =
                make_float2(vB.x + b0 + hB.x, vB.y + b1 + hB.y);
        }
    }
    __syncthreads();
    // LayerNorm per row, write out
    {
        float* s_o = (float*)(smem + NK_O);
#pragma unroll
        for (int it = 0; it < 8; it++) {
            int row = wid * 8 + it;
            int n = n0 + row;
            float4 o = *(const float4*)(s_o + row * 132 + lane * 4);
            float s = o.x + o.y + o.z + o.w;
#pragma unroll
            for (int off = 16; off > 0; off >>= 1)
                s += __shfl_xor_sync(0xffffffffu, s, off);
            float mean = s * (1.f / 128.f);
            float dx = o.x - mean, dy = o.y - mean, dz = o.z - mean, dw = o.w - mean;
            float q = dx * dx + dy * dy + dz * dz + dw * dw;
#pragma unroll
            for (int off = 16; off > 0; off >>= 1)
                q += __shfl_xor_sync(0xffffffffu, q, off);
            float inv = rsqrtf(q * (1.f / 128.f) + 1e-5f);
            float4 g4 = *(const float4*)(s_lng + lane * 4);
            float4 bb = *(const float4*)(s_lnb + lane * 4);
            float4 y;
            y.x = dx * inv * g4.x + bb.x;
            y.y = dy * inv * g4.y + bb.y;
            y.z = dz * inv * g4.z + bb.z;
            y.w = dw * inv * g4.w + bb.w;
            if (n < N) ((float4*)out)[(size_t)n * 32 + lane] = y;
        }
    }
}

// ---------------- x output ---------------------------------------------------
__global__ void coord_out_kernel(const float* __restrict__ x,
                                 const float* __restrict__ logit,
                                 float* __restrict__ out_x, int N)
{
    int n = blockIdx.x * blockDim.x + threadIdx.x;
    if (n < N) {
        if (g_skip_coord) {
            out_x[n * 3 + 0] = x[n * 3 + 0];
            out_x[n * 3 + 1] = x[n * 3 + 1];
            out_x[n * 3 + 2] = x[n * 3 + 2];
        } else {
            float scale = 1.f / (1.f + expf(-logit[0]));
            float dg = fmaxf(g_deg[n], 1.f);
            float inv = scale / dg;
            out_x[n * 3 + 0] = x[n * 3 + 0] + g_delta[n * 3 + 0] * inv;
            out_x[n * 3 + 1] = x[n * 3 + 1] + g_delta[n * 3 + 1] * inv;
            out_x[n * 3 + 2] = x[n * 3 + 2] + g_delta[n * 3 + 2] * inv;
        }
    }
}

// ---------------- launcher ----------------------------------------------------
extern "C" void kernel_launch(void* const* d_in, const int* in_sizes, int n_in,
                              void* d_out, int out_size)
{
    const float* h   = (const float*)d_in[0];
    const float* x   = (const float*)d_in[1];
    const void*  ei  = d_in[2];
    const float* ea  = (const float*)d_in[3];
    const float* ew1 = (const float*)d_in[4];
    const float* eb1 = (const float*)d_in[5];
    const float* ew2 = (const float*)d_in[6];
    const float* eb2 = (const float*)d_in[7];
    const float* nw1 = (const float*)d_in[8];
    const float* nb1 = (const float*)d_in[9];
    const float* nw2 = (const float*)d_in[10];
    const float* nb2 = (const float*)d_in[11];
    const float* cw1 = (const float*)d_in[12];
    const float* cb1 = (const float*)d_in[13];
    const float* cw2 = (const float*)d_in[14];
    const float* cb2 = (const float*)d_in[15];
    const float* lgt = (const float*)d_in[16];
    const float* lng = (const float*)d_in[17];
    const float* lnb = (const float*)d_in[18];

    const int N = in_sizes[0] / 128;
    const int E = in_sizes[3] / 4;

    float* out_h = (float*)d_out;
    float* out_x = out_h + (size_t)N * 128;

    cudaFuncSetAttribute(proj_hmma, cudaFuncAttributeMaxDynamicSharedMemorySize,
                         PROJ_SMEM_BYTES);
    cudaFuncSetAttribute(edge_tc_kernel, cudaFuncAttributeMaxDynamicSharedMemorySize,
                         EDGE_SMEM_BYTES);
    cudaFuncSetAttribute(node_hmma, cudaFuncAttributeMaxDynamicSharedMemorySize,
                         NODE_SMEM_BYTES);

    detect_kernel<<<1, 32>>>((const unsigned int*)ei, cw2, cb2);
    zero_kernel<<<(N * 128 + 255) / 256, 256>>>(N);
    build_b_kernel<<<128, 256>>>(ew2, ew1, nw1, nw2);
    proj_hmma<<<(N + 127) / 128, 512, PROJ_SMEM_BYTES>>>(h, eb1, N);
    edge_tc_kernel<<<(E + 255) / 256, 512, EDGE_SMEM_BYTES>>>(
        x, ei, ea, ew1, eb2, cw1, cb1, cw2, cb2, E);
    node_hmma<<<(N + 127) / 128, 512, NODE_SMEM_BYTES>>>(
        h, nb1, nb2, lng, lnb, out_h, N);
    coord_out_kernel<<<(N + 255) / 256, 256>>>(x, lgt, out_x, N);
}

// round 12
// speedup vs baseline: 1.0512x; 1.0512x over previous
#include <cuda_runtime.h>
#include <cuda_bf16.h>
#include <cuda_fp16.h>
#include <cstdint>

#define NMAX 50000

extern __shared__ __align__(1024) char smem_raw[];

// ---------------- scratch ----------------------------------------------------
__device__ float g_agg[NMAX * 128];
__device__ __align__(16) unsigned short g_P1h[NMAX * 128];  // fp16: h@W_d + eb1
__device__ __align__(16) unsigned short g_P2h[NMAX * 128];  // fp16: h@W_s
__device__ float g_delta[NMAX * 3];
__device__ float g_deg[NMAX];
__device__ int   g_is64;
__device__ int   g_skip_coord;
// fp16 weight images, row-major [out n][in k]
__device__ __align__(16) unsigned short g_Bh[16384];    // ew2^T
__device__ __align__(16) unsigned short g_Bd[16384];    // ew1[0:128]^T
__device__ __align__(16) unsigned short g_Bs[16384];    // ew1[128:256]^T
__device__ __align__(16) unsigned short g_Bn1[32768];   // nw1^T [128][256]
__device__ __align__(16) unsigned short g_Bn2[16384];   // nw2^T [128][128]

__device__ __forceinline__ float silu_f(float v) { return v / (1.f + __expf(-v)); }

// ---------------- ptx helpers ----------------------------------------------
#define LDSM_X4(r, addr) \
    asm volatile("ldmatrix.sync.aligned.m8n8.x4.shared.b16 {%0,%1,%2,%3}, [%4];" \
        : "=r"((r)[0]), "=r"((r)[1]), "=r"((r)[2]), "=r"((r)[3]) : "r"(addr))

// fp16-accumulate HMMA: D/C are 2 packed half2 regs.
__device__ __forceinline__ void mma16816h(uint32_t* d, const uint32_t* a, const uint32_t* b) {
    asm volatile("mma.sync.aligned.m16n8k16.row.col.f16.f16.f16.f16 "
        "{%0,%1}, {%2,%3,%4,%5}, {%6,%7}, {%0,%1};"
        : "+r"(d[0]), "+r"(d[1])
        : "r"(a[0]), "r"(a[1]), "r"(a[2]), "r"(a[3]), "r"(b[0]), "r"(b[1]));
}

__device__ __forceinline__ void red_add_v4(float* p, float a, float b, float c, float d) {
    asm volatile("red.global.add.v4.f32 [%0], {%1, %2, %3, %4};"
        :: "l"(p), "f"(a), "f"(b), "f"(c), "f"(d) : "memory");
}

__device__ __forceinline__ float2 h2f2(uint32_t u) {
    __half2 h = *(__half2*)&u;
    return __half22float2(h);
}

#define APITCH  136
#define AROWB   272
#define TILE_B  (128 * AROWB)        // 34816 bytes per fp16 tile

// ---------------- probes -----------------------------------------------------
__global__ void detect_kernel(const unsigned int* __restrict__ w,
                              const float* __restrict__ cw2,
                              const float* __restrict__ cb2) {
    if (threadIdx.x == 0) {
        int all0 = 1;
#pragma unroll
        for (int i = 1; i < 64; i += 2) all0 &= (w[i] == 0u);
        g_is64 = all0;
        int z = (cb2[0] == 0.f);
        for (int i = 0; i < 64; i++) z &= (cw2[i] == 0.f);
        g_skip_coord = z;
    }
}

__global__ void zero_kernel(int n) {
    int i = blockIdx.x * blockDim.x + threadIdx.x;
    if (i < n * 128) g_agg[i] = 0.f;
    if (i < n * 3)   g_delta[i] = 0.f;
    if (i < n)       g_deg[i] = 0.f;
}

// build all fp16 weight images
__global__ void build_b_kernel(const float* __restrict__ ew2,
                               const float* __restrict__ ew1,
                               const float* __restrict__ nw1,
                               const float* __restrict__ nw2) {
    int idx = blockIdx.x * 256 + threadIdx.x;   // 0..32767
    if (idx < 16384) {
        int j = idx >> 7, k = idx & 127;
        g_Bh[j * 128 + k] = __half_as_ushort(__float2half_rn(ew2[k * 128 + j]));
        g_Bd[j * 128 + k] = __half_as_ushort(__float2half_rn(ew1[k * 128 + j]));
        g_Bs[j * 128 + k] = __half_as_ushort(__float2half_rn(ew1[(128 + k) * 128 + j]));
        g_Bn2[j * 128 + k] = __half_as_ushort(__float2half_rn(nw2[k * 128 + j]));
    }
    {
        int j = idx >> 8, k = idx & 255;        // [128][256]
        g_Bn1[j * 256 + k] = __half_as_ushort(__float2half_rn(nw1[k * 128 + j]));
    }
}

// ---------------- HMMA proj kernel: P1h, P2h --------------------------------
#define PK_EB1  0
#define PK_A    1024
#define PK_BD   (PK_A + TILE_B)
#define PK_BS   (PK_BD + TILE_B)
#define PROJ_SMEM_BYTES (PK_BS + TILE_B)   // 105472

__global__ __launch_bounds__(512, 2) void proj_hmma(
    const float* __restrict__ h, const float* __restrict__ eb1, int N)
{
    char* smem = smem_raw;
    const uint32_t sb = (uint32_t)__cvta_generic_to_shared(smem);
    float* s_eb1 = (float*)(smem + PK_EB1);
    const int tid = threadIdx.x, wid = tid >> 5, lane = tid & 31;
    const int n0 = blockIdx.x * 128;

    if (tid < 32) *(float4*)(s_eb1 + tid * 4) = __ldg((const float4*)eb1 + tid);
    for (int i = tid; i < 128 * 16; i += 512) {
        int rw = i >> 4, c = i & 15;
        *(uint4*)(smem + PK_BD + rw * AROWB + c * 16) = ((const uint4*)g_Bd)[rw * 16 + c];
        *(uint4*)(smem + PK_BS + rw * AROWB + c * 16) = ((const uint4*)g_Bs)[rw * 16 + c];
    }
#pragma unroll
    for (int it = 0; it < 8; it++) {
        int row = wid * 8 + it;
        int n = n0 + row;
        float4 v = make_float4(0.f, 0.f, 0.f, 0.f);
        if (n < N) v = __ldg((const float4*)h + (size_t)n * 32 + lane);
        __half2 h01 = __floats2half2_rn(v.x, v.y);
        __half2 h23 = __floats2half2_rn(v.z, v.w);
        uint2 u; u.x = *(uint32_t*)&h01; u.y = *(uint32_t*)&h23;
        *(uint2*)(smem + PK_A + row * AROWB + lane * 8) = u;
    }
    __syncthreads();

    const int mw = wid & 7, nw = wid >> 3;   // 8 M-warps x 2 N-warps
    const int mi = lane >> 3, r = lane & 7;
    const uint32_t aBase = sb + PK_A
        + (uint32_t)((mw * 16 + (mi & 1) * 8 + r) * APITCH + (mi >> 1) * 8) * 2u;
    const uint32_t bBase = sb + PK_BD
        + (uint32_t)((nw * 64 + (mi >> 1) * 8 + r) * APITCH + (mi & 1) * 8) * 2u;
    const int gid = lane >> 2, tig = lane & 3;

    uint32_t c[8][2];
#pragma unroll
    for (int pass = 0; pass < 2; pass++) {
#pragma unroll
        for (int nt = 0; nt < 8; nt++) { c[nt][0] = 0u; c[nt][1] = 0u; }
        uint32_t bb = bBase + pass * (PK_BS - PK_BD);
#pragma unroll
        for (int ks = 0; ks < 8; ks++) {
            uint32_t af[4];
            LDSM_X4(af, aBase + ks * 32);
            uint32_t kb = bb + ks * 32;
#pragma unroll
            for (int np = 0; np < 4; np++) {
                uint32_t bf[4];
                LDSM_X4(bf, kb);
                mma16816h(c[2*np],   af, bf + 0);
                mma16816h(c[2*np+1], af, bf + 2);
                kb += 16 * AROWB;
            }
        }
        unsigned short* dst = pass == 0 ? g_P1h : g_P2h;
        int rA = mw * 16 + gid;
        int nA = n0 + rA, nB = nA + 8;
#pragma unroll
        for (int nt = 0; nt < 8; nt++) {
            int col = nw * 64 + nt * 8 + tig * 2;
            float b0 = pass == 0 ? s_eb1[col] : 0.f;
            float b1 = pass == 0 ? s_eb1[col + 1] : 0.f;
            float2 vA = h2f2(c[nt][0]);
            float2 vB = h2f2(c[nt][1]);
            if (nA < N)
                *(__half2*)(dst + (size_t)nA * 128 + col) =
                    __floats2half2_rn(vA.x + b0, vA.y + b1);
            if (nB < N)
                *(__half2*)(dst + (size_t)nB * 128 + col) =
                    __floats2half2_rn(vB.x + b0, vB.y + b1);
        }
    }
}

// ---------------- HMMA edge kernel (2 tiles of 128 edges per block) ----------
#define EK_DST   0
#define EK_SRC   512
#define EK_DSQ   1024
#define EK_DIST  1536
#define EK_REL   2048
#define EK_EA    3584
#define EK_TAIL  5632
#define EK_EB2   8192
#define EK_A     8704
#define EK_B     (EK_A + TILE_B)
#define EK_MSG   EK_A
#define EDGE_SMEM_BYTES (EK_B + TILE_B)   // 78336
#define EDGE_TILES 2

__global__ __launch_bounds__(512, 2) void edge_tc_kernel(
    const float* __restrict__ x,
    const void*  __restrict__ eidx, const float* __restrict__ eattr,
    const float* __restrict__ ew1, const float* __restrict__ eb2,
    const float* __restrict__ cw1, const float* __restrict__ cb1,
    const float* __restrict__ cw2, const float* __restrict__ cb2,
    int E)
{
    char* smem = smem_raw;
    const uint32_t sb = (uint32_t)__cvta_generic_to_shared(smem);
    int*   s_dst  = (int*)(smem + EK_DST);
    int*   s_src  = (int*)(smem + EK_SRC);
    float* s_dsq  = (float*)(smem + EK_DSQ);
    float* s_dist = (float*)(smem + EK_DIST);
    float* s_rel  = (float*)(smem + EK_REL);
    float* s_ea   = (float*)(smem + EK_EA);
    float* s_tail = (float*)(smem + EK_TAIL);
    float* s_eb2  = (float*)(smem + EK_EB2);

    const int tid  = threadIdx.x;
    const int wid  = tid >> 5;
    const int lane = tid & 31;

    // ---- once per block: tail weights, eb2, B tile ----
    if (tid >= 128 && tid < 288) {
        int t = tid - 128;
        int r = t >> 5, c = t & 31;
        *(float4*)(s_tail + r * 128 + c * 4) =
            __ldg((const float4*)(ew1 + (256 + r) * 128) + c);
    }
    if (tid >= 288 && tid < 320)
        *(float4*)(s_eb2 + (tid - 288) * 4) = __ldg((const float4*)eb2 + (tid - 288));
    for (int i = tid; i < 128 * 16; i += 512) {
        int rw = i >> 4, c = i & 15;
        *(uint4*)(smem + EK_B + rw * AROWB + c * 16) = ((const uint4*)g_Bh)[rw * 16 + c];
    }

    const int mw = wid & 7;
    const int nw = wid >> 3;
    const int mi = lane >> 3, r = lane & 7;
    const uint32_t aBase = sb + EK_A
        + (uint32_t)((mw * 16 + (mi & 1) * 8 + r) * APITCH + (mi >> 1) * 8) * 2u;
    const uint32_t bBase = sb + EK_B
        + (uint32_t)((nw * 64 + (mi >> 1) * 8 + r) * APITCH + (mi & 1) * 8) * 2u;
    const int gid = lane >> 2, tig = lane & 3;

    for (int t = 0; t < EDGE_TILES; t++) {
        const int e0 = (blockIdx.x * EDGE_TILES + t) * 128;
        if (e0 >= E) break;
        __syncthreads();   // orders prior epilogue reads / LDSM before overwrite

        // ---- stage 1: per-edge scalars ----
        if (tid < 128) {
            int ge = e0 + tid;
            int dI = -1, sI = 0;
            float rx = 0.f, ry = 0.f, rz = 0.f, dsq = 1e-8f;
            float4 ea = make_float4(0.f, 0.f, 0.f, 0.f);
            if (ge < E) {
                if (g_is64) {
                    const long long* p = (const long long*)eidx;
                    sI = (int)p[ge]; dI = (int)p[E + ge];
                } else {
                    const int* p = (const int*)eidx;
                    sI = p[ge]; dI = p[E + ge];
                }
                const float* xd = x + (size_t)dI * 3;
                const float* xs = x + (size_t)sI * 3;
                rx = xd[0] - xs[0]; ry = xd[1] - xs[1]; rz = xd[2] - xs[2];
                dsq = fmaxf(rx * rx + ry * ry + rz * rz, 1e-8f);
                ea = ((const float4*)eattr)[ge];
            }
            s_dst[tid] = dI; s_src[tid] = sI;
            s_rel[tid * 3 + 0] = rx; s_rel[tid * 3 + 1] = ry; s_rel[tid * 3 + 2] = rz;
            s_dist[tid] = sqrtf(dsq);
            s_dsq[tid]  = dsq;
            *(float4*)(s_ea + tid * 4) = ea;
        }
        __syncthreads();

        // ---- gather fp16 P1/P2 + tail + silu -> fp16 A tile ----
#pragma unroll
        for (int it = 0; it < 8; it++) {
            int e  = wid * 8 + it;
            int dI = s_dst[e];
            float4 v = make_float4(0.f, 0.f, 0.f, 0.f);
            if (dI >= 0) {
                uint2 ua = *(const uint2*)(g_P1h + (size_t)dI * 128 + lane * 4);
                uint2 ub = *(const uint2*)(g_P2h + (size_t)s_src[e] * 128 + lane * 4);
                __half2 a01 = *(__half2*)&ua.x, a23 = *(__half2*)&ua.y;
                __half2 b01 = *(__half2*)&ub.x, b23 = *(__half2*)&ub.y;
                float ds = s_dsq[e];
                float4 ea = *(const float4*)(s_ea + e * 4);
                float4 wd = *(const float4*)(s_tail + 0 * 128 + lane * 4);
                float4 a0 = *(const float4*)(s_tail + 1 * 128 + lane * 4);
                float4 a1 = *(const float4*)(s_tail + 2 * 128 + lane * 4);
                float4 a2 = *(const float4*)(s_tail + 3 * 128 + lane * 4);
                float4 a3 = *(const float4*)(s_tail + 4 * 128 + lane * 4);
                v.x = __low2float(a01)  + __low2float(b01)
                    + fmaf(ds,wd.x,fmaf(ea.x,a0.x,fmaf(ea.y,a1.x,fmaf(ea.z,a2.x,ea.w*a3.x))));
                v.y = __high2float(a01) + __high2float(b01)
                    + fmaf(ds,wd.y,fmaf(ea.x,a0.y,fmaf(ea.y,a1.y,fmaf(ea.z,a2.y,ea.w*a3.y))));
                v.z = __low2float(a23)  + __low2float(b23)
                    + fmaf(ds,wd.z,fmaf(ea.x,a0.z,fmaf(ea.y,a1.z,fmaf(ea.z,a2.z,ea.w*a3.z))));
                v.w = __high2float(a23) + __high2float(b23)
                    + fmaf(ds,wd.w,fmaf(ea.x,a0.w,fmaf(ea.y,a1.w,fmaf(ea.z,a2.w,ea.w*a3.w))));
                v.x = silu_f(v.x); v.y = silu_f(v.y); v.z = silu_f(v.z); v.w = silu_f(v.w);
            }
            __half2 h01 = __floats2half2_rn(v.x, v.y);
            __half2 h23 = __floats2half2_rn(v.z, v.w);
            uint2 u; u.x = *(uint32_t*)&h01; u.y = *(uint32_t*)&h23;
            *(uint2*)(smem + EK_A + e * AROWB + lane * 8) = u;
        }
        __syncthreads();

        // ---- fp16 HMMA (f16 accum), each warp D[16 x 64] ----
        uint32_t c[8][2];
#pragma unroll
        for (int nt = 0; nt < 8; nt++) { c[nt][0] = 0u; c[nt][1] = 0u; }
#pragma unroll
        for (int ks = 0; ks < 8; ks++) {
            uint32_t af[4];
            LDSM_X4(af, aBase + ks * 32);
            uint32_t kb = bBase + ks * 32;
#pragma unroll
            for (int np = 0; np < 4; np++) {
                uint32_t bf[4];
                LDSM_X4(bf, kb);
                mma16816h(c[2*np],   af, bf + 0);
                mma16816h(c[2*np+1], af, bf + 2);
                kb += 16 * AROWB;
            }
        }

        // ---- bias + silu; pair-shuffle v4 reductions into g_agg ----
        const int skip = g_skip_coord;
        {
            int rA = mw * 16 + gid;
            int rB = rA + 8;
            int dA = s_dst[rA], dB = s_dst[rB];
#pragma unroll
            for (int nt = 0; nt < 8; nt++) {
                int col = nw * 64 + nt * 8 + tig * 2;
                float b0 = s_eb2[col], b1 = s_eb2[col + 1];
                float2 vA = h2f2(c[nt][0]);
                float2 vB = h2f2(c[nt][1]);
                float mA0 = silu_f(vA.x + b0), mA1 = silu_f(vA.y + b1);
                float mB0 = silu_f(vB.x + b0), mB1 = silu_f(vB.y + b1);
                float pA0 = __shfl_down_sync(0xffffffffu, mA0, 1);
                float pA1 = __shfl_down_sync(0xffffffffu, mA1, 1);
                float pB0 = __shfl_down_sync(0xffffffffu, mB0, 1);
                float pB1 = __shfl_down_sync(0xffffffffu, mB1, 1);
                if ((tig & 1) == 0) {
                    if (dA >= 0)
                        red_add_v4(g_agg + (size_t)dA * 128 + col, mA0, mA1, pA0, pA1);
                    if (dB >= 0)
                        red_add_v4(g_agg + (size_t)dB * 128 + col, mB0, mB1, pB0, pB1);
                }
            }
        }

        if (skip) continue;

        // ---- fallback coord path ----
        __syncthreads();
        {
            float* s_msg = (float*)(smem + EK_MSG);
            int rA = mw * 16 + gid;
            int rB = rA + 8;
#pragma unroll
            for (int nt = 0; nt < 8; nt++) {
                int col = nw * 64 + nt * 8 + tig * 2;
                float b0 = s_eb2[col], b1 = s_eb2[col + 1];
                float2 vA = h2f2(c[nt][0]);
                float2 vB = h2f2(c[nt][1]);
                *(float2*)(s_msg + rA * 128 + col) =
                    make_float2(silu_f(vA.x + b0), silu_f(vA.y + b1));
                *(float2*)(s_msg + rB * 128 + col) =
                    make_float2(silu_f(vB.x + b0), silu_f(vB.y + b1));
            }
        }
        __syncthreads();
        {
            float* s_msg = (float*)(smem + EK_MSG);
            const int jc = tid & 15;
            const int ec = tid >> 4;   // 32 groups x 4 edges
            float4 acc3[4];
#pragma unroll
            for (int e = 0; e < 4; e++) acc3[e] = make_float4(0.f, 0.f, 0.f, 0.f);
            const float4* C1 = (const float4*)cw1;
            const float* sM = s_msg + ec * 4 * 128;
#pragma unroll 2
            for (int k4 = 0; k4 < 32; k4++) {
                const int kb = k4 * 4;
                float4 w0 = __ldg(C1 + (kb + 0) * 16 + jc);
                float4 w1 = __ldg(C1 + (kb + 1) * 16 + jc);
                float4 w2 = __ldg(C1 + (kb + 2) * 16 + jc);
                float4 w3 = __ldg(C1 + (kb + 3) * 16 + jc);
#pragma unroll
                for (int e = 0; e < 4; e++) {
                    float4 a = *(const float4*)(sM + e * 128 + kb);
                    acc3[e].x = fmaf(a.x,w0.x,fmaf(a.y,w1.x,fmaf(a.z,w2.x,fmaf(a.w,w3.x,acc3[e].x))));
                    acc3[e].y = fmaf(a.x,w0.y,fmaf(a.y,w1.y,fmaf(a.z,w2.y,fmaf(a.w,w3.y,acc3[e].y))));
                    acc3[e].z = fmaf(a.x,w0.z,fmaf(a.y,w1.z,fmaf(a.z,w2.z,fmaf(a.w,w3.z,acc3[e].z))));
                    acc3[e].w = fmaf(a.x,w0.w,fmaf(a.y,w1.w,fmaf(a.z,w2.w,fmaf(a.w,w3.w,acc3[e].w))));
                }
            }
            float4 bc = __ldg((const float4*)cb1 + jc);
            float4 c2 = __ldg((const float4*)cw2 + jc);
            float part[4];
#pragma unroll
            for (int e = 0; e < 4; e++) {
                float cx = silu_f(acc3[e].x + bc.x);
                float cy = silu_f(acc3[e].y + bc.y);
                float cz = silu_f(acc3[e].z + bc.z);
                float cw_ = silu_f(acc3[e].w + bc.w);
                part[e] = cx * c2.x + cy * c2.y + cz * c2.z + cw_ * c2.w;
            }
#pragma unroll
            for (int off = 8; off > 0; off >>= 1) {
#pragma unroll
                for (int e = 0; e < 4; e++)
                    part[e] += __shfl_xor_sync(0xffffffffu, part[e], off, 16);
            }
            if (jc == 0) {
                float cb2v = __ldg(cb2);
#pragma unroll
                for (int e = 0; e < 4; e++) {
                    int ee = ec * 4 + e;
                    int dI = s_dst[ee];
                    if (dI >= 0) {
                        float wv = part[e] + cb2v;
                        float f = wv / (s_dist[ee] + 1.f);
                        atomicAdd(&g_delta[dI * 3 + 0], s_rel[ee * 3 + 0] * f);
                        atomicAdd(&g_delta[dI * 3 + 1], s_rel[ee * 3 + 1] * f);
                        atomicAdd(&g_delta[dI * 3 + 2], s_rel[ee * 3 + 2] * f);
                        atomicAdd(&g_deg[dI], 1.f);
                    }
                }
            }
        }
    }
}

// ---------------- HMMA node kernel ------------------------------------------
#define NK_NB1   0
#define NK_NB2   512
#define NK_LNG   1024
#define NK_LNB   1536
#define NK_A     2048
#define NK_B0    (NK_A + TILE_B)
#define NK_B1    (NK_B0 + TILE_B)
#define NK_O     2048
#define NODE_SMEM_BYTES (NK_B1 + TILE_B)   // 106496

__global__ __launch_bounds__(512, 2) void node_hmma(
    const float* __restrict__ h,
    const float* __restrict__ nb1, const float* __restrict__ nb2,
    const float* __restrict__ ln_g, const float* __restrict__ ln_b,
    float* __restrict__ out, int N)
{
    char* smem = smem_raw;
    const uint32_t sb = (uint32_t)__cvta_generic_to_shared(smem);
    float* s_nb1 = (float*)(smem + NK_NB1);
    float* s_nb2 = (float*)(smem + NK_NB2);
    float* s_lng = (float*)(smem + NK_LNG);
    float* s_lnb = (float*)(smem + NK_LNB);
    const int tid = threadIdx.x, wid = tid >> 5, lane = tid & 31;
    const int n0 = blockIdx.x * 128;

    if (tid < 32) {
        *(float4*)(s_nb1 + tid * 4) = __ldg((const float4*)nb1 + tid);
        *(float4*)(s_nb2 + tid * 4) = __ldg((const float4*)nb2 + tid);
        *(float4*)(s_lng + tid * 4) = __ldg((const float4*)ln_g + tid);
        *(float4*)(s_lnb + tid * 4) = __ldg((const float4*)ln_b + tid);
    }
    for (int i = tid; i < 128 * 16; i += 512) {
        int rw = i >> 4, c = i & 15;
        *(uint4*)(smem + NK_B0 + rw * AROWB + c * 16) = ((const uint4*)g_Bn1)[rw * 32 + c];
        *(uint4*)(smem + NK_B1 + rw * AROWB + c * 16) = ((const uint4*)g_Bn1)[rw * 32 + 16 + c];
    }
#pragma unroll
    for (int it = 0; it < 8; it++) {
        int row = wid * 8 + it;
        int n = n0 + row;
        float4 v = make_float4(0.f, 0.f, 0.f, 0.f);
        if (n < N) v = __ldg((const float4*)h + (size_t)n * 32 + lane);
        __half2 h01 = __floats2half2_rn(v.x, v.y);
        __half2 h23 = __floats2half2_rn(v.z, v.w);
        uint2 u; u.x = *(uint32_t*)&h01; u.y = *(uint32_t*)&h23;
        *(uint2*)(smem + NK_A + row * AROWB + lane * 8) = u;
    }
    __syncthreads();

    const int mw = wid & 7, nw = wid >> 3;
    const int mi = lane >> 3, r = lane & 7;
    const uint32_t aBase = sb + NK_A
        + (uint32_t)((mw * 16 + (mi & 1) * 8 + r) * APITCH + (mi >> 1) * 8) * 2u;
    const uint32_t bBase0 = sb + NK_B0
        + (uint32_t)((nw * 64 + (mi >> 1) * 8 + r) * APITCH + (mi & 1) * 8) * 2u;
    const int gid = lane >> 2, tig = lane & 3;

    uint32_t c[8][2];
#pragma unroll
    for (int nt = 0; nt < 8; nt++) { c[nt][0] = 0u; c[nt][1] = 0u; }

    // layer 1, k-half 0 (A = h fp16)
#pragma unroll
    for (int ks = 0; ks < 8; ks++) {
        uint32_t af[4];
        LDSM_X4(af, aBase + ks * 32);
        uint32_t kb = bBase0 + ks * 32;
#pragma unroll
        for (int np = 0; np < 4; np++) {
            uint32_t bf[4];
            LDSM_X4(bf, kb);
            mma16816h(c[2*np],   af, bf + 0);
            mma16816h(c[2*np+1], af, bf + 2);
            kb += 16 * AROWB;
        }
    }
    __syncthreads();
#pragma unroll
    for (int it = 0; it < 8; it++) {
        int row = wid * 8 + it;
        int n = n0 + row;
        float4 v = make_float4(0.f, 0.f, 0.f, 0.f);
        if (n < N) v = *((const float4*)g_agg + (size_t)n * 32 + lane);
        __half2 h01 = __floats2half2_rn(v.x, v.y);
        __half2 h23 = __floats2half2_rn(v.z, v.w);
        uint2 u; u.x = *(uint32_t*)&h01; u.y = *(uint32_t*)&h23;
        *(uint2*)(smem + NK_A + row * AROWB + lane * 8) = u;
    }
    __syncthreads();
    // layer 1, k-half 1 (A = agg)
#pragma unroll
    for (int ks = 0; ks < 8; ks++) {
        uint32_t af[4];
        LDSM_X4(af, aBase + ks * 32);
        uint32_t kb = bBase0 + (NK_B1 - NK_B0) + ks * 32;
#pragma unroll
        for (int np = 0; np < 4; np++) {
            uint32_t bf[4];
            LDSM_X4(bf, kb);
            mma16816h(c[2*np],   af, bf + 0);
            mma16816h(c[2*np+1], af, bf + 2);
            kb += 16 * AROWB;
        }
    }
    __syncthreads();
    // t1 = silu(c + nb1) -> fp16 into NK_A; Bn2 -> NK_B0
    {
        int rA = mw * 16 + gid;
        int rB = rA + 8;
#pragma unroll
        for (int nt = 0; nt < 8; nt++) {
            int col = nw * 64 + nt * 8 + tig * 2;
            float b0 = s_nb1[col], b1 = s_nb1[col + 1];
            float2 vA = h2f2(c[nt][0]);
            float2 vB = h2f2(c[nt][1]);
            *(__half2*)(smem + NK_A + rA * AROWB + col * 2) =
                __floats2half2_rn(silu_f(vA.x + b0), silu_f(vA.y + b1));
            *(__half2*)(smem + NK_A + rB * AROWB + col * 2) =
                __floats2half2_rn(silu_f(vB.x + b0), silu_f(vB.y + b1));
        }
    }
    for (int i = tid; i < 128 * 16; i += 512) {
        int rw = i >> 4, cc = i & 15;
        *(uint4*)(smem + NK_B0 + rw * AROWB + cc * 16) = ((const uint4*)g_Bn2)[rw * 16 + cc];
    }
    __syncthreads();

    // layer 2
#pragma unroll
    for (int nt = 0; nt < 8; nt++) { c[nt][0] = 0u; c[nt][1] = 0u; }
#pragma unroll
    for (int ks = 0; ks < 8; ks++) {
        uint32_t af[4];
        LDSM_X4(af, aBase + ks * 32);
        uint32_t kb = bBase0 + ks * 32;
#pragma unroll
        for (int np = 0; np < 4; np++) {
            uint32_t bf[4];
            LDSM_X4(bf, kb);
            mma16816h(c[2*np],   af, bf + 0);
            mma16816h(c[2*np+1], af, bf + 2);
            kb += 16 * AROWB;
        }
    }
    __syncthreads();
    // stage o = c + nb2 + h (residual) fp32 into NK_O (pitch 132)
    {
        float* s_o = (float*)(smem + NK_O);
        int rA = mw * 16 + gid;
        int rB = rA + 8;
        int nA = n0 + rA, nB = n0 + rB;
#pragma unroll
        for (int nt = 0; nt < 8; nt++) {
            int col = nw * 64 + nt * 8 + tig * 2;
            float b0 = s_nb2[col], b1 = s_nb2[col + 1];
            float2 hA = make_float2(0.f, 0.f), hB = make_float2(0.f, 0.f);
            if (nA < N) hA = *(const float2*)(h + (size_t)nA * 128 + col);
            if (nB < N) hB = *(const float2*)(h + (size_t)nB * 128 + col);
            float2 vA = h2f2(c[nt][0]);
            float2 vB = h2f2(c[nt][1]);
            *(float2*)(s_o + rA * 132 + col) =
                make_float2(vA.x + b0 + hA.x, vA.y + b1 + hA.y);
            *(float2*)(s_o + rB * 132 + col) =
                make_float2(vB.x + b0 + hB.x, vB.y + b1 + hB.y);
        }
    }
    __syncthreads();
    // LayerNorm per row, write out
    {
        float* s_o = (float*)(smem + NK_O);
#pragma unroll
        for (int it = 0; it < 8; it++) {
            int row = wid * 8 + it;
            int n = n0 + row;
            float4 o = *(const float4*)(s_o + row * 132 + lane * 4);
            float s = o.x + o.y + o.z + o.w;
#pragma unroll
            for (int off = 16; off > 0; off >>= 1)
                s += __shfl_xor_sync(0xffffffffu, s, off);
            float mean = s * (1.f / 128.f);
            float dx = o.x - mean, dy = o.y - mean, dz = o.z - mean, dw = o.w - mean;
            float q = dx * dx + dy * dy + dz * dz + dw * dw;
#pragma unroll
            for (int off = 16; off > 0; off >>= 1)
                q += __shfl_xor_sync(0xffffffffu, q, off);
            float inv = rsqrtf(q * (1.f / 128.f) + 1e-5f);
            float4 g4 = *(const float4*)(s_lng + lane * 4);
            float4 bb = *(const float4*)(s_lnb + lane * 4);
            float4 y;
            y.x = dx * inv * g4.x + bb.x;
            y.y = dy * inv * g4.y + bb.y;
            y.z = dz * inv * g4.z + bb.z;
            y.w = dw * inv * g4.w + bb.w;
            if (n < N) ((float4*)out)[(size_t)n * 32 + lane] = y;
        }
    }
}

// ---------------- x output ---------------------------------------------------
__global__ void coord_out_kernel(const float* __restrict__ x,
                                 const float* __restrict__ logit,
                                 float* __restrict__ out_x, int N)
{
    int n = blockIdx.x * blockDim.x + threadIdx.x;
    if (n < N) {
        if (g_skip_coord) {
            out_x[n * 3 + 0] = x[n * 3 + 0];
            out_x[n * 3 + 1] = x[n * 3 + 1];
            out_x[n * 3 + 2] = x[n * 3 + 2];
        } else {
            float scale = 1.f / (1.f + expf(-logit[0]));
            float dg = fmaxf(g_deg[n], 1.f);
            float inv = scale / dg;
            out_x[n * 3 + 0] = x[n * 3 + 0] + g_delta[n * 3 + 0] * inv;
            out_x[n * 3 + 1] = x[n * 3 + 1] + g_delta[n * 3 + 1] * inv;
            out_x[n * 3 + 2] = x[n * 3 + 2] + g_delta[n * 3 + 2] * inv;
        }
    }
}

// ---------------- launcher ----------------------------------------------------
extern "C" void kernel_launch(void* const* d_in, const int* in_sizes, int n_in,
                              void* d_out, int out_size)
{
    const float* h   = (const float*)d_in[0];
    const float* x   = (const float*)d_in[1];
    const void*  ei  = d_in[2];
    const float* ea  = (const float*)d_in[3];
    const float* ew1 = (const float*)d_in[4];
    const float* eb1 = (const float*)d_in[5];
    const float* ew2 = (const float*)d_in[6];
    const float* eb2 = (const float*)d_in[7];
    const float* nw1 = (const float*)d_in[8];
    const float* nb1 = (const float*)d_in[9];
    const float* nw2 = (const float*)d_in[10];
    const float* nb2 = (const float*)d_in[11];
    const float* cw1 = (const float*)d_in[12];
    const float* cb1 = (const float*)d_in[13];
    const float* cw2 = (const float*)d_in[14];
    const float* cb2 = (const float*)d_in[15];
    const float* lgt = (const float*)d_in[16];
    const float* lng = (const float*)d_in[17];
    const float* lnb = (const float*)d_in[18];

    const int N = in_sizes[0] / 128;
    const int E = in_sizes[3] / 4;

    float* out_h = (float*)d_out;
    float* out_x = out_h + (size_t)N * 128;

    cudaFuncSetAttribute(proj_hmma, cudaFuncAttributeMaxDynamicSharedMemorySize,
                         PROJ_SMEM_BYTES);
    cudaFuncSetAttribute(edge_tc_kernel, cudaFuncAttributeMaxDynamicSharedMemorySize,
                         EDGE_SMEM_BYTES);
    cudaFuncSetAttribute(node_hmma, cudaFuncAttributeMaxDynamicSharedMemorySize,
                         NODE_SMEM_BYTES);

    detect_kernel<<<1, 32>>>((const unsigned int*)ei, cw2, cb2);
    zero_kernel<<<(N * 128 + 511) / 512, 512>>>(N);
    build_b_kernel<<<128, 256>>>(ew2, ew1, nw1, nw2);
    proj_hmma<<<(N + 127) / 128, 512, PROJ_SMEM_BYTES>>>(h, eb1, N);
    edge_tc_kernel<<<(E + 255) / 256, 512, EDGE_SMEM_BYTES>>>(
        x, ei, ea, ew1, eb2, cw1, cb1, cw2, cb2, E);
    node_hmma<<<(N + 127) / 128, 512, NODE_SMEM_BYTES>>>(
        h, nb1, nb2, lng, lnb, out_h, N);
    coord_out_kernel<<<(N + 255) / 256, 256>>>(x, lgt, out_x, N);
}

// round 13
// speedup vs baseline: 1.0977x; 1.0443x over previous
#include <cuda_runtime.h>
#include <cuda_bf16.h>
#include <cuda_fp16.h>
#include <cstdint>

#define NMAX 50000

extern __shared__ __align__(1024) char smem_raw[];

// ---------------- scratch ----------------------------------------------------
__device__ float g_agg[NMAX * 128];
__device__ __align__(16) unsigned short g_P1h[NMAX * 128];  // fp16: h@W_d + eb1
__device__ __align__(16) unsigned short g_P2h[NMAX * 128];  // fp16: h@W_s
__device__ float g_delta[NMAX * 3];
__device__ float g_deg[NMAX];
__device__ int   g_is64;
__device__ int   g_skip_coord;
// fp16 weight images, row-major [out n][in k]
__device__ __align__(16) unsigned short g_Bh[16384];    // ew2^T
__device__ __align__(16) unsigned short g_Bd[16384];    // ew1[0:128]^T
__device__ __align__(16) unsigned short g_Bs[16384];    // ew1[128:256]^T
__device__ __align__(16) unsigned short g_Bn1[32768];   // nw1^T [128][256]
__device__ __align__(16) unsigned short g_Bn2[16384];   // nw2^T [128][128]

__device__ __forceinline__ float silu_f(float v) { return v / (1.f + __expf(-v)); }

// ---------------- ptx helpers ----------------------------------------------
#define LDSM_X4(r, addr) \
    asm volatile("ldmatrix.sync.aligned.m8n8.x4.shared.b16 {%0,%1,%2,%3}, [%4];" \
        : "=r"((r)[0]), "=r"((r)[1]), "=r"((r)[2]), "=r"((r)[3]) : "r"(addr))

// fp16-accumulate HMMA: D/C are 2 packed half2 regs.
__device__ __forceinline__ void mma16816h(uint32_t* d, const uint32_t* a, const uint32_t* b) {
    asm volatile("mma.sync.aligned.m16n8k16.row.col.f16.f16.f16.f16 "
        "{%0,%1}, {%2,%3,%4,%5}, {%6,%7}, {%0,%1};"
        : "+r"(d[0]), "+r"(d[1])
        : "r"(a[0]), "r"(a[1]), "r"(a[2]), "r"(a[3]), "r"(b[0]), "r"(b[1]));
}

__device__ __forceinline__ void red_add_v4(float* p, float a, float b, float c, float d) {
    asm volatile("red.global.add.v4.f32 [%0], {%1, %2, %3, %4};"
        :: "l"(p), "f"(a), "f"(b), "f"(c), "f"(d) : "memory");
}

__device__ __forceinline__ float2 h2f2(uint32_t u) {
    __half2 h = *(__half2*)&u;
    return __half22float2(h);
}

#define APITCH  136
#define AROWB   272
#define TILE_B  (128 * AROWB)        // 34816 bytes per fp16 tile

// ---------------- fused setup kernel -----------------------------------------
// grid: (N*128 + 511)/512 blocks of 512. Covers zeroing (agg/delta/deg),
// probes (block 0 thread 0), and weight-image builds (first 64 blocks).
__global__ void setup_kernel(const unsigned int* __restrict__ w,
                             const float* __restrict__ cw2,
                             const float* __restrict__ cb2,
                             const float* __restrict__ ew2,
                             const float* __restrict__ ew1,
                             const float* __restrict__ nw1,
                             const float* __restrict__ nw2,
                             int n)
{
    int i = blockIdx.x * blockDim.x + threadIdx.x;
    if (i == 0) {
        int all0 = 1;
#pragma unroll
        for (int k = 1; k < 64; k += 2) all0 &= (w[k] == 0u);
        g_is64 = all0;
        int z = (cb2[0] == 0.f);
        for (int k = 0; k < 64; k++) z &= (cw2[k] == 0.f);
        g_skip_coord = z;
    }
    if (i < n * 128) g_agg[i] = 0.f;
    if (i < n * 3)   g_delta[i] = 0.f;
    if (i < n)       g_deg[i] = 0.f;
    if (i < 16384) {
        int j = i >> 7, k = i & 127;
        g_Bh[j * 128 + k]  = __half_as_ushort(__float2half_rn(ew2[k * 128 + j]));
        g_Bd[j * 128 + k]  = __half_as_ushort(__float2half_rn(ew1[k * 128 + j]));
        g_Bs[j * 128 + k]  = __half_as_ushort(__float2half_rn(ew1[(128 + k) * 128 + j]));
        g_Bn2[j * 128 + k] = __half_as_ushort(__float2half_rn(nw2[k * 128 + j]));
    }
    if (i < 32768) {
        int j = i >> 8, k = i & 255;        // [128][256]
        g_Bn1[j * 256 + k] = __half_as_ushort(__float2half_rn(nw1[k * 128 + j]));
    }
}

// ---------------- HMMA proj kernel: P1h, P2h --------------------------------
#define PK_EB1  0
#define PK_A    1024
#define PK_BD   (PK_A + TILE_B)
#define PK_BS   (PK_BD + TILE_B)
#define PROJ_SMEM_BYTES (PK_BS + TILE_B)   // 105472

__global__ __launch_bounds__(512, 2) void proj_hmma(
    const float* __restrict__ h, const float* __restrict__ eb1, int N)
{
    char* smem = smem_raw;
    const uint32_t sb = (uint32_t)__cvta_generic_to_shared(smem);
    float* s_eb1 = (float*)(smem + PK_EB1);
    const int tid = threadIdx.x, wid = tid >> 5, lane = tid & 31;
    const int n0 = blockIdx.x * 128;

    if (tid < 32) *(float4*)(s_eb1 + tid * 4) = __ldg((const float4*)eb1 + tid);
    for (int i = tid; i < 128 * 16; i += 512) {
        int rw = i >> 4, c = i & 15;
        *(uint4*)(smem + PK_BD + rw * AROWB + c * 16) = ((const uint4*)g_Bd)[rw * 16 + c];
        *(uint4*)(smem + PK_BS + rw * AROWB + c * 16) = ((const uint4*)g_Bs)[rw * 16 + c];
    }
#pragma unroll
    for (int it = 0; it < 8; it++) {
        int row = wid * 8 + it;
        int n = n0 + row;
        float4 v = make_float4(0.f, 0.f, 0.f, 0.f);
        if (n < N) v = __ldg((const float4*)h + (size_t)n * 32 + lane);
        __half2 h01 = __floats2half2_rn(v.x, v.y);
        __half2 h23 = __floats2half2_rn(v.z, v.w);
        uint2 u; u.x = *(uint32_t*)&h01; u.y = *(uint32_t*)&h23;
        *(uint2*)(smem + PK_A + row * AROWB + lane * 8) = u;
    }
    __syncthreads();

    const int mw = wid & 7, nw = wid >> 3;   // 8 M-warps x 2 N-warps
    const int mi = lane >> 3, r = lane & 7;
    const uint32_t aBase = sb + PK_A
        + (uint32_t)((mw * 16 + (mi & 1) * 8 + r) * APITCH + (mi >> 1) * 8) * 2u;
    const uint32_t bBase = sb + PK_BD
        + (uint32_t)((nw * 64 + (mi >> 1) * 8 + r) * APITCH + (mi & 1) * 8) * 2u;
    const int gid = lane >> 2, tig = lane & 3;

    uint32_t c[8][2];
#pragma unroll
    for (int pass = 0; pass < 2; pass++) {
#pragma unroll
        for (int nt = 0; nt < 8; nt++) { c[nt][0] = 0u; c[nt][1] = 0u; }
        uint32_t bb = bBase + pass * (PK_BS - PK_BD);
#pragma unroll
        for (int ks = 0; ks < 8; ks++) {
            uint32_t af[4];
            LDSM_X4(af, aBase + ks * 32);
            uint32_t kb = bb + ks * 32;
#pragma unroll
            for (int np = 0; np < 4; np++) {
                uint32_t bf[4];
                LDSM_X4(bf, kb);
                mma16816h(c[2*np],   af, bf + 0);
                mma16816h(c[2*np+1], af, bf + 2);
                kb += 16 * AROWB;
            }
        }
        unsigned short* dst = pass == 0 ? g_P1h : g_P2h;
        int rA = mw * 16 + gid;
        int nA = n0 + rA, nB = nA + 8;
#pragma unroll
        for (int nt = 0; nt < 8; nt++) {
            int col = nw * 64 + nt * 8 + tig * 2;
            float b0 = pass == 0 ? s_eb1[col] : 0.f;
            float b1 = pass == 0 ? s_eb1[col + 1] : 0.f;
            float2 vA = h2f2(c[nt][0]);
            float2 vB = h2f2(c[nt][1]);
            if (nA < N)
                *(__half2*)(dst + (size_t)nA * 128 + col) =
                    __floats2half2_rn(vA.x + b0, vA.y + b1);
            if (nB < N)
                *(__half2*)(dst + (size_t)nB * 128 + col) =
                    __floats2half2_rn(vB.x + b0, vB.y + b1);
        }
    }
}

// ---------------- HMMA edge kernel ------------------------------------------
#define EK_DST   0
#define EK_SRC   512
#define EK_DSQ   1024
#define EK_DIST  1536
#define EK_REL   2048
#define EK_EA    3584
#define EK_TAIL  5632
#define EK_EB2   8192
#define EK_A     8704
#define EK_B     (EK_A + TILE_B)
#define EK_MSG   EK_A
#define EDGE_SMEM_BYTES (EK_B + TILE_B)   // 78336

__global__ __launch_bounds__(512, 2) void edge_tc_kernel(
    const float* __restrict__ x,
    const void*  __restrict__ eidx, const float* __restrict__ eattr,
    const float* __restrict__ ew1, const float* __restrict__ eb2,
    const float* __restrict__ cw1, const float* __restrict__ cb1,
    const float* __restrict__ cw2, const float* __restrict__ cb2,
    int E)
{
    char* smem = smem_raw;
    const uint32_t sb = (uint32_t)__cvta_generic_to_shared(smem);
    int*   s_dst  = (int*)(smem + EK_DST);
    int*   s_src  = (int*)(smem + EK_SRC);
    float* s_dsq  = (float*)(smem + EK_DSQ);
    float* s_dist = (float*)(smem + EK_DIST);
    float* s_rel  = (float*)(smem + EK_REL);
    float* s_ea   = (float*)(smem + EK_EA);
    float* s_tail = (float*)(smem + EK_TAIL);
    float* s_eb2  = (float*)(smem + EK_EB2);

    const int tid  = threadIdx.x;
    const int wid  = tid >> 5;
    const int lane = tid & 31;
    const int e0   = blockIdx.x * 128;

    if (tid < 128) {
        int ge = e0 + tid;
        int dI = -1, sI = 0;
        float rx = 0.f, ry = 0.f, rz = 0.f, dsq = 1e-8f;
        float4 ea = make_float4(0.f, 0.f, 0.f, 0.f);
        if (ge < E) {
            if (g_is64) {
                const long long* p = (const long long*)eidx;
                sI = (int)p[ge]; dI = (int)p[E + ge];
            } else {
                const int* p = (const int*)eidx;
                sI = p[ge]; dI = p[E + ge];
            }
            const float* xd = x + (size_t)dI * 3;
            const float* xs = x + (size_t)sI * 3;
            rx = xd[0] - xs[0]; ry = xd[1] - xs[1]; rz = xd[2] - xs[2];
            dsq = fmaxf(rx * rx + ry * ry + rz * rz, 1e-8f);
            ea = ((const float4*)eattr)[ge];
        }
        s_dst[tid] = dI; s_src[tid] = sI;
        s_rel[tid * 3 + 0] = rx; s_rel[tid * 3 + 1] = ry; s_rel[tid * 3 + 2] = rz;
        s_dist[tid] = sqrtf(dsq);
        s_dsq[tid]  = dsq;
        *(float4*)(s_ea + tid * 4) = ea;
    }
    if (tid >= 128 && tid < 288) {
        int t = tid - 128;
        int r = t >> 5, c = t & 31;
        *(float4*)(s_tail + r * 128 + c * 4) =
            __ldg((const float4*)(ew1 + (256 + r) * 128) + c);
    }
    if (tid >= 288 && tid < 320)
        *(float4*)(s_eb2 + (tid - 288) * 4) = __ldg((const float4*)eb2 + (tid - 288));
    for (int i = tid; i < 128 * 16; i += 512) {
        int rw = i >> 4, c = i & 15;
        *(uint4*)(smem + EK_B + rw * AROWB + c * 16) = ((const uint4*)g_Bh)[rw * 16 + c];
    }
    __syncthreads();

    // ---- gather fp16 P1/P2 + tail + silu -> fp16 A tile (8 edges/warp) ----
#pragma unroll
    for (int it = 0; it < 8; it++) {
        int e  = wid * 8 + it;
        int dI = s_dst[e];
        float4 v = make_float4(0.f, 0.f, 0.f, 0.f);
        if (dI >= 0) {
            uint2 ua = *(const uint2*)(g_P1h + (size_t)dI * 128 + lane * 4);
            uint2 ub = *(const uint2*)(g_P2h + (size_t)s_src[e] * 128 + lane * 4);
            __half2 a01 = *(__half2*)&ua.x, a23 = *(__half2*)&ua.y;
            __half2 b01 = *(__half2*)&ub.x, b23 = *(__half2*)&ub.y;
            float ds = s_dsq[e];
            float4 ea = *(const float4*)(s_ea + e * 4);
            float4 wd = *(const float4*)(s_tail + 0 * 128 + lane * 4);
            float4 a0 = *(const float4*)(s_tail + 1 * 128 + lane * 4);
            float4 a1 = *(const float4*)(s_tail + 2 * 128 + lane * 4);
            float4 a2 = *(const float4*)(s_tail + 3 * 128 + lane * 4);
            float4 a3 = *(const float4*)(s_tail + 4 * 128 + lane * 4);
            v.x = __low2float(a01)  + __low2float(b01)
                + fmaf(ds,wd.x,fmaf(ea.x,a0.x,fmaf(ea.y,a1.x,fmaf(ea.z,a2.x,ea.w*a3.x))));
            v.y = __high2float(a01) + __high2float(b01)
                + fmaf(ds,wd.y,fmaf(ea.x,a0.y,fmaf(ea.y,a1.y,fmaf(ea.z,a2.y,ea.w*a3.y))));
            v.z = __low2float(a23)  + __low2float(b23)
                + fmaf(ds,wd.z,fmaf(ea.x,a0.z,fmaf(ea.y,a1.z,fmaf(ea.z,a2.z,ea.w*a3.z))));
            v.w = __high2float(a23) + __high2float(b23)
                + fmaf(ds,wd.w,fmaf(ea.x,a0.w,fmaf(ea.y,a1.w,fmaf(ea.z,a2.w,ea.w*a3.w))));
            v.x = silu_f(v.x); v.y = silu_f(v.y); v.z = silu_f(v.z); v.w = silu_f(v.w);
        }
        __half2 h01 = __floats2half2_rn(v.x, v.y);
        __half2 h23 = __floats2half2_rn(v.z, v.w);
        uint2 u; u.x = *(uint32_t*)&h01; u.y = *(uint32_t*)&h23;
        *(uint2*)(smem + EK_A + e * AROWB + lane * 8) = u;
    }
    __syncthreads();

    // ---- fp16 HMMA (f16 accum), each warp D[16 x 64] ----
    const int mw = wid & 7;
    const int nw = wid >> 3;
    uint32_t c[8][2];
#pragma unroll
    for (int nt = 0; nt < 8; nt++) { c[nt][0] = 0u; c[nt][1] = 0u; }
    {
        const int mi = lane >> 3, r = lane & 7;
        uint32_t aBase = sb + EK_A
            + (uint32_t)((mw * 16 + (mi & 1) * 8 + r) * APITCH + (mi >> 1) * 8) * 2u;
        uint32_t bBase = sb + EK_B
            + (uint32_t)((nw * 64 + (mi >> 1) * 8 + r) * APITCH + (mi & 1) * 8) * 2u;
#pragma unroll
        for (int ks = 0; ks < 8; ks++) {
            uint32_t af[4];
            LDSM_X4(af, aBase + ks * 32);
            uint32_t kb = bBase + ks * 32;
#pragma unroll
            for (int np = 0; np < 4; np++) {
                uint32_t bf[4];
                LDSM_X4(bf, kb);
                mma16816h(c[2*np],   af, bf + 0);
                mma16816h(c[2*np+1], af, bf + 2);
                kb += 16 * AROWB;
            }
        }
    }

    // ---- bias + silu; pair-shuffle v4 reductions into g_agg ----
    const int gid = lane >> 2, tig = lane & 3;
    const int skip = g_skip_coord;
    {
        int rA = mw * 16 + gid;
        int rB = rA + 8;
        int dA = s_dst[rA], dB = s_dst[rB];
#pragma unroll
        for (int nt = 0; nt < 8; nt++) {
            int col = nw * 64 + nt * 8 + tig * 2;
            float b0 = s_eb2[col], b1 = s_eb2[col + 1];
            float2 vA = h2f2(c[nt][0]);
            float2 vB = h2f2(c[nt][1]);
            float mA0 = silu_f(vA.x + b0), mA1 = silu_f(vA.y + b1);
            float mB0 = silu_f(vB.x + b0), mB1 = silu_f(vB.y + b1);
            float pA0 = __shfl_down_sync(0xffffffffu, mA0, 1);
            float pA1 = __shfl_down_sync(0xffffffffu, mA1, 1);
            float pB0 = __shfl_down_sync(0xffffffffu, mB0, 1);
            float pB1 = __shfl_down_sync(0xffffffffu, mB1, 1);
            if ((tig & 1) == 0) {
                if (dA >= 0)
                    red_add_v4(g_agg + (size_t)dA * 128 + col, mA0, mA1, pA0, pA1);
                if (dB >= 0)
                    red_add_v4(g_agg + (size_t)dB * 128 + col, mB0, mB1, pB0, pB1);
            }
        }
    }

    if (skip) return;

    // ---- fallback coord path ----
    __syncthreads();
    {
        float* s_msg = (float*)(smem + EK_MSG);
        int rA = mw * 16 + gid;
        int rB = rA + 8;
#pragma unroll
        for (int nt = 0; nt < 8; nt++) {
            int col = nw * 64 + nt * 8 + tig * 2;
            float b0 = s_eb2[col], b1 = s_eb2[col + 1];
            float2 vA = h2f2(c[nt][0]);
            float2 vB = h2f2(c[nt][1]);
            *(float2*)(s_msg + rA * 128 + col) =
                make_float2(silu_f(vA.x + b0), silu_f(vA.y + b1));
            *(float2*)(s_msg + rB * 128 + col) =
                make_float2(silu_f(vB.x + b0), silu_f(vB.y + b1));
        }
    }
    __syncthreads();
    {
        float* s_msg = (float*)(smem + EK_MSG);
        const int jc = tid & 15;
        const int ec = tid >> 4;   // 32 groups x 4 edges
        float4 acc3[4];
#pragma unroll
        for (int e = 0; e < 4; e++) acc3[e] = make_float4(0.f, 0.f, 0.f, 0.f);
        const float4* C1 = (const float4*)cw1;
        const float* sM = s_msg + ec * 4 * 128;
#pragma unroll 2
        for (int k4 = 0; k4 < 32; k4++) {
            const int kb = k4 * 4;
            float4 w0 = __ldg(C1 + (kb + 0) * 16 + jc);
            float4 w1 = __ldg(C1 + (kb + 1) * 16 + jc);
            float4 w2 = __ldg(C1 + (kb + 2) * 16 + jc);
            float4 w3 = __ldg(C1 + (kb + 3) * 16 + jc);
#pragma unroll
            for (int e = 0; e < 4; e++) {
                float4 a = *(const float4*)(sM + e * 128 + kb);
                acc3[e].x = fmaf(a.x,w0.x,fmaf(a.y,w1.x,fmaf(a.z,w2.x,fmaf(a.w,w3.x,acc3[e].x))));
                acc3[e].y = fmaf(a.x,w0.y,fmaf(a.y,w1.y,fmaf(a.z,w2.y,fmaf(a.w,w3.y,acc3[e].y))));
                acc3[e].z = fmaf(a.x,w0.z,fmaf(a.y,w1.z,fmaf(a.z,w2.z,fmaf(a.w,w3.z,acc3[e].z))));
                acc3[e].w = fmaf(a.x,w0.w,fmaf(a.y,w1.w,fmaf(a.z,w2.w,fmaf(a.w,w3.w,acc3[e].w))));
            }
        }
        float4 bc = __ldg((const float4*)cb1 + jc);
        float4 c2 = __ldg((const float4*)cw2 + jc);
        float part[4];
#pragma unroll
        for (int e = 0; e < 4; e++) {
            float cx = silu_f(acc3[e].x + bc.x);
            float cy = silu_f(acc3[e].y + bc.y);
            float cz = silu_f(acc3[e].z + bc.z);
            float cw_ = silu_f(acc3[e].w + bc.w);
            part[e] = cx * c2.x + cy * c2.y + cz * c2.z + cw_ * c2.w;
        }
#pragma unroll
        for (int off = 8; off > 0; off >>= 1) {
#pragma unroll
            for (int e = 0; e < 4; e++)
                part[e] += __shfl_xor_sync(0xffffffffu, part[e], off, 16);
        }
        if (jc == 0) {
            float cb2v = __ldg(cb2);
#pragma unroll
            for (int e = 0; e < 4; e++) {
                int ee = ec * 4 + e;
                int dI = s_dst[ee];
                if (dI >= 0) {
                    float wv = part[e] + cb2v;
                    float f = wv / (s_dist[ee] + 1.f);
                    atomicAdd(&g_delta[dI * 3 + 0], s_rel[ee * 3 + 0] * f);
                    atomicAdd(&g_delta[dI * 3 + 1], s_rel[ee * 3 + 1] * f);
                    atomicAdd(&g_delta[dI * 3 + 2], s_rel[ee * 3 + 2] * f);
                    atomicAdd(&g_deg[dI], 1.f);
                }
            }
        }
    }
}

// ---------------- HMMA node kernel ------------------------------------------
#define NK_NB1   0
#define NK_NB2   512
#define NK_LNG   1024
#define NK_LNB   1536
#define NK_A     2048
#define NK_B0    (NK_A + TILE_B)
#define NK_B1    (NK_B0 + TILE_B)
#define NK_O     2048
#define NODE_SMEM_BYTES (NK_B1 + TILE_B)   // 106496

__global__ __launch_bounds__(512, 2) void node_hmma(
    const float* __restrict__ h,
    const float* __restrict__ nb1, const float* __restrict__ nb2,
    const float* __restrict__ ln_g, const float* __restrict__ ln_b,
    float* __restrict__ out, int N)
{
    char* smem = smem_raw;
    const uint32_t sb = (uint32_t)__cvta_generic_to_shared(smem);
    float* s_nb1 = (float*)(smem + NK_NB1);
    float* s_nb2 = (float*)(smem + NK_NB2);
    float* s_lng = (float*)(smem + NK_LNG);
    float* s_lnb = (float*)(smem + NK_LNB);
    const int tid = threadIdx.x, wid = tid >> 5, lane = tid & 31;
    const int n0 = blockIdx.x * 128;

    if (tid < 32) {
        *(float4*)(s_nb1 + tid * 4) = __ldg((const float4*)nb1 + tid);
        *(float4*)(s_nb2 + tid * 4) = __ldg((const float4*)nb2 + tid);
        *(float4*)(s_lng + tid * 4) = __ldg((const float4*)ln_g + tid);
        *(float4*)(s_lnb + tid * 4) = __ldg((const float4*)ln_b + tid);
    }
    for (int i = tid; i < 128 * 16; i += 512) {
        int rw = i >> 4, c = i & 15;
        *(uint4*)(smem + NK_B0 + rw * AROWB + c * 16) = ((const uint4*)g_Bn1)[rw * 32 + c];
        *(uint4*)(smem + NK_B1 + rw * AROWB + c * 16) = ((const uint4*)g_Bn1)[rw * 32 + 16 + c];
    }
#pragma unroll
    for (int it = 0; it < 8; it++) {
        int row = wid * 8 + it;
        int n = n0 + row;
        float4 v = make_float4(0.f, 0.f, 0.f, 0.f);
        if (n < N) v = __ldg((const float4*)h + (size_t)n * 32 + lane);
        __half2 h01 = __floats2half2_rn(v.x, v.y);
        __half2 h23 = __floats2half2_rn(v.z, v.w);
        uint2 u; u.x = *(uint32_t*)&h01; u.y = *(uint32_t*)&h23;
        *(uint2*)(smem + NK_A + row * AROWB + lane * 8) = u;
    }
    __syncthreads();

    const int mw = wid & 7, nw = wid >> 3;
    const int mi = lane >> 3, r = lane & 7;
    const uint32_t aBase = sb + NK_A
        + (uint32_t)((mw * 16 + (mi & 1) * 8 + r) * APITCH + (mi >> 1) * 8) * 2u;
    const uint32_t bBase0 = sb + NK_B0
        + (uint32_t)((nw * 64 + (mi >> 1) * 8 + r) * APITCH + (mi & 1) * 8) * 2u;
    const int gid = lane >> 2, tig = lane & 3;

    uint32_t c[8][2];
#pragma unroll
    for (int nt = 0; nt < 8; nt++) { c[nt][0] = 0u; c[nt][1] = 0u; }

    // layer 1, k-half 0 (A = h fp16)
#pragma unroll
    for (int ks = 0; ks < 8; ks++) {
        uint32_t af[4];
        LDSM_X4(af, aBase + ks * 32);
        uint32_t kb = bBase0 + ks * 32;
#pragma unroll
        for (int np = 0; np < 4; np++) {
            uint32_t bf[4];
            LDSM_X4(bf, kb);
            mma16816h(c[2*np],   af, bf + 0);
            mma16816h(c[2*np+1], af, bf + 2);
            kb += 16 * AROWB;
        }
    }
    __syncthreads();
#pragma unroll
    for (int it = 0; it < 8; it++) {
        int row = wid * 8 + it;
        int n = n0 + row;
        float4 v = make_float4(0.f, 0.f, 0.f, 0.f);
        if (n < N) v = *((const float4*)g_agg + (size_t)n * 32 + lane);
        __half2 h01 = __floats2half2_rn(v.x, v.y);
        __half2 h23 = __floats2half2_rn(v.z, v.w);
        uint2 u; u.x = *(uint32_t*)&h01; u.y = *(uint32_t*)&h23;
        *(uint2*)(smem + NK_A + row * AROWB + lane * 8) = u;
    }
    __syncthreads();
    // layer 1, k-half 1 (A = agg)
#pragma unroll
    for (int ks = 0; ks < 8; ks++) {
        uint32_t af[4];
        LDSM_X4(af, aBase + ks * 32);
        uint32_t kb = bBase0 + (NK_B1 - NK_B0) + ks * 32;
#pragma unroll
        for (int np = 0; np < 4; np++) {
            uint32_t bf[4];
            LDSM_X4(bf, kb);
            mma16816h(c[2*np],   af, bf + 0);
            mma16816h(c[2*np+1], af, bf + 2);
            kb += 16 * AROWB;
        }
    }
    __syncthreads();
    // t1 = silu(c + nb1) -> fp16 into NK_A; Bn2 -> NK_B0
    {
        int rA = mw * 16 + gid;
        int rB = rA + 8;
#pragma unroll
        for (int nt = 0; nt < 8; nt++) {
            int col = nw * 64 + nt * 8 + tig * 2;
            float b0 = s_nb1[col], b1 = s_nb1[col + 1];
            float2 vA = h2f2(c[nt][0]);
            float2 vB = h2f2(c[nt][1]);
            *(__half2*)(smem + NK_A + rA * AROWB + col * 2) =
                __floats2half2_rn(silu_f(vA.x + b0), silu_f(vA.y + b1));
            *(__half2*)(smem + NK_A + rB * AROWB + col * 2) =
                __floats2half2_rn(silu_f(vB.x + b0), silu_f(vB.y + b1));
        }
    }
    for (int i = tid; i < 128 * 16; i += 512) {
        int rw = i >> 4, cc = i & 15;
        *(uint4*)(smem + NK_B0 + rw * AROWB + cc * 16) = ((const uint4*)g_Bn2)[rw * 16 + cc];
    }
    __syncthreads();

    // layer 2
#pragma unroll
    for (int nt = 0; nt < 8; nt++) { c[nt][0] = 0u; c[nt][1] = 0u; }
#pragma unroll
    for (int ks = 0; ks < 8; ks++) {
        uint32_t af[4];
        LDSM_X4(af, aBase + ks * 32);
        uint32_t kb = bBase0 + ks * 32;
#pragma unroll
        for (int np = 0; np < 4; np++) {
            uint32_t bf[4];
            LDSM_X4(bf, kb);
            mma16816h(c[2*np],   af, bf + 0);
            mma16816h(c[2*np+1], af, bf + 2);
            kb += 16 * AROWB;
        }
    }
    __syncthreads();
    // stage o = c + nb2 + h (residual) fp32 into NK_O (pitch 132)
    {
        float* s_o = (float*)(smem + NK_O);
        int rA = mw * 16 + gid;
        int rB = rA + 8;
        int nA = n0 + rA, nB = n0 + rB;
#pragma unroll
        for (int nt = 0; nt < 8; nt++) {
            int col = nw * 64 + nt * 8 + tig * 2;
            float b0 = s_nb2[col], b1 = s_nb2[col + 1];
            float2 hA = make_float2(0.f, 0.f), hB = make_float2(0.f, 0.f);
            if (nA < N) hA = *(const float2*)(h + (size_t)nA * 128 + col);
            if (nB < N) hB = *(const float2*)(h + (size_t)nB * 128 + col);
            float2 vA = h2f2(c[nt][0]);
            float2 vB = h2f2(c[nt][1]);
            *(float2*)(s_o + rA * 132 + col) =
                make_float2(vA.x + b0 + hA.x, vA.y + b1 + hA.y);
            *(float2*)(s_o + rB * 132 + col) =
                make_float2(vB.x + b0 + hB.x, vB.y + b1 + hB.y);
        }
    }
    __syncthreads();
    // LayerNorm per row, write out
    {
        float* s_o = (float*)(smem + NK_O);
#pragma unroll
        for (int it = 0; it < 8; it++) {
            int row = wid * 8 + it;
            int n = n0 + row;
            float4 o = *(const float4*)(s_o + row * 132 + lane * 4);
            float s = o.x + o.y + o.z + o.w;
#pragma unroll
            for (int off = 16; off > 0; off >>= 1)
                s += __shfl_xor_sync(0xffffffffu, s, off);
            float mean = s * (1.f / 128.f);
            float dx = o.x - mean, dy = o.y - mean, dz = o.z - mean, dw = o.w - mean;
            float q = dx * dx + dy * dy + dz * dz + dw * dw;
#pragma unroll
            for (int off = 16; off > 0; off >>= 1)
                q += __shfl_xor_sync(0xffffffffu, q, off);
            float inv = rsqrtf(q * (1.f / 128.f) + 1e-5f);
            float4 g4 = *(const float4*)(s_lng + lane * 4);
            float4 bb = *(const float4*)(s_lnb + lane * 4);
            float4 y;
            y.x = dx * inv * g4.x + bb.x;
            y.y = dy * inv * g4.y + bb.y;
            y.z = dz * inv * g4.z + bb.z;
            y.w = dw * inv * g4.w + bb.w;
            if (n < N) ((float4*)out)[(size_t)n * 32 + lane] = y;
        }
    }
}

// ---------------- x output ---------------------------------------------------
__global__ void coord_out_kernel(const float* __restrict__ x,
                                 const float* __restrict__ logit,
                                 float* __restrict__ out_x, int N)
{
    int n = blockIdx.x * blockDim.x + threadIdx.x;
    if (n < N) {
        if (g_skip_coord) {
            out_x[n * 3 + 0] = x[n * 3 + 0];
            out_x[n * 3 + 1] = x[n * 3 + 1];
            out_x[n * 3 + 2] = x[n * 3 + 2];
        } else {
            float scale = 1.f / (1.f + expf(-logit[0]));
            float dg = fmaxf(g_deg[n], 1.f);
            float inv = scale / dg;
            out_x[n * 3 + 0] = x[n * 3 + 0] + g_delta[n * 3 + 0] * inv;
            out_x[n * 3 + 1] = x[n * 3 + 1] + g_delta[n * 3 + 1] * inv;
            out_x[n * 3 + 2] = x[n * 3 + 2] + g_delta[n * 3 + 2] * inv;
        }
    }
}

// ---------------- launcher ----------------------------------------------------
extern "C" void kernel_launch(void* const* d_in, const int* in_sizes, int n_in,
                              void* d_out, int out_size)
{
    const float* h   = (const float*)d_in[0];
    const float* x   = (const float*)d_in[1];
    const void*  ei  = d_in[2];
    const float* ea  = (const float*)d_in[3];
    const float* ew1 = (const float*)d_in[4];
    const float* eb1 = (const float*)d_in[5];
    const float* ew2 = (const float*)d_in[6];
    const float* eb2 = (const float*)d_in[7];
    const float* nw1 = (const float*)d_in[8];
    const float* nb1 = (const float*)d_in[9];
    const float* nw2 = (const float*)d_in[10];
    const float* nb2 = (const float*)d_in[11];
    const float* cw1 = (const float*)d_in[12];
    const float* cb1 = (const float*)d_in[13];
    const float* cw2 = (const float*)d_in[14];
    const float* cb2 = (const float*)d_in[15];
    const float* lgt = (const float*)d_in[16];
    const float* lng = (const float*)d_in[17];
    const float* lnb = (const float*)d_in[18];

    const int N = in_sizes[0] / 128;
    const int E = in_sizes[3] / 4;

    float* out_h = (float*)d_out;
    float* out_x = out_h + (size_t)N * 128;

    cudaFuncSetAttribute(proj_hmma, cudaFuncAttributeMaxDynamicSharedMemorySize,
                         PROJ_SMEM_BYTES);
    cudaFuncSetAttribute(edge_tc_kernel, cudaFuncAttributeMaxDynamicSharedMemorySize,
                         EDGE_SMEM_BYTES);
    cudaFuncSetAttribute(node_hmma, cudaFuncAttributeMaxDynamicSharedMemorySize,
                         NODE_SMEM_BYTES);

    setup_kernel<<<(N * 128 + 511) / 512, 512>>>(
        (const unsigned int*)ei, cw2, cb2, ew2, ew1, nw1, nw2, N);
    proj_hmma<<<(N + 127) / 128, 512, PROJ_SMEM_BYTES>>>(h, eb1, N);
    edge_tc_kernel<<<(E + 127) / 128, 512, EDGE_SMEM_BYTES>>>(
        x, ei, ea, ew1, eb2, cw1, cb1, cw2, cb2, E);
    node_hmma<<<(N + 127) / 128, 512, NODE_SMEM_BYTES>>>(
        h, nb1, nb2, lng, lnb, out_h, N);
    coord_out_kernel<<<(N + 255) / 256, 256>>>(x, lgt, out_x, N);
}

// round 14
// speedup vs baseline: 1.1195x; 1.0198x over previous
#include <cuda_runtime.h>
#include <cuda_bf16.h>
#include <cuda_fp16.h>
#include <cstdint>

#define NMAX 50000

extern __shared__ __align__(1024) char smem_raw[];

// ---------------- scratch ----------------------------------------------------
__device__ float g_agg[NMAX * 128];
__device__ __align__(16) unsigned short g_P1h[NMAX * 128];  // fp16: h@W_d + eb1
__device__ __align__(16) unsigned short g_P2h[NMAX * 128];  // fp16: h@W_s
__device__ float g_delta[NMAX * 3];
__device__ float g_deg[NMAX];
__device__ int   g_is64;
__device__ int   g_skip_coord;
// fp16 weight images, row-major [out n][in k]
__device__ __align__(16) unsigned short g_Bh[16384];    // ew2^T
__device__ __align__(16) unsigned short g_Bd[16384];    // ew1[0:128]^T
__device__ __align__(16) unsigned short g_Bs[16384];    // ew1[128:256]^T
__device__ __align__(16) unsigned short g_Bn1[32768];   // nw1^T [128][256]
__device__ __align__(16) unsigned short g_Bn2[16384];   // nw2^T [128][128]

__device__ __forceinline__ float silu_f(float v) { return v / (1.f + __expf(-v)); }

// ---------------- ptx helpers ----------------------------------------------
#define LDSM_X4(r, addr) \
    asm volatile("ldmatrix.sync.aligned.m8n8.x4.shared.b16 {%0,%1,%2,%3}, [%4];" \
        : "=r"((r)[0]), "=r"((r)[1]), "=r"((r)[2]), "=r"((r)[3]) : "r"(addr))

// fp16-accumulate HMMA: D/C are 2 packed half2 regs.
__device__ __forceinline__ void mma16816h(uint32_t* d, const uint32_t* a, const uint32_t* b) {
    asm volatile("mma.sync.aligned.m16n8k16.row.col.f16.f16.f16.f16 "
        "{%0,%1}, {%2,%3,%4,%5}, {%6,%7}, {%0,%1};"
        : "+r"(d[0]), "+r"(d[1])
        : "r"(a[0]), "r"(a[1]), "r"(a[2]), "r"(a[3]), "r"(b[0]), "r"(b[1]));
}

__device__ __forceinline__ void red_add_v4(float* p, float a, float b, float c, float d) {
    asm volatile("red.global.add.v4.f32 [%0], {%1, %2, %3, %4};"
        :: "l"(p), "f"(a), "f"(b), "f"(c), "f"(d) : "memory");
}

__device__ __forceinline__ float2 h2f2(uint32_t u) {
    __half2 h = *(__half2*)&u;
    return __half22float2(h);
}

#define APITCH  136
#define AROWB   272
#define TILE_B  (128 * AROWB)        // 34816 bytes per fp16 tile

// ---------------- fused setup kernel -----------------------------------------
// grid: (N*32 + 511)/512 blocks of 512 (float4 strides over g_agg).
__global__ void setup_kernel(const unsigned int* __restrict__ w,
                             const float* __restrict__ cw2,
                             const float* __restrict__ cb2,
                             const float* __restrict__ ew2,
                             const float* __restrict__ ew1,
                             const float* __restrict__ nw1,
                             const float* __restrict__ nw2,
                             int n)
{
    int i = blockIdx.x * blockDim.x + threadIdx.x;
    if (i == 0) {
        int all0 = 1;
#pragma unroll
        for (int k = 1; k < 64; k += 2) all0 &= (w[k] == 0u);
        g_is64 = all0;
        int z = (cb2[0] == 0.f);
        for (int k = 0; k < 64; k++) z &= (cw2[k] == 0.f);
        g_skip_coord = z;
    }
    float4 z4 = make_float4(0.f, 0.f, 0.f, 0.f);
    if (i < n * 32) ((float4*)g_agg)[i] = z4;
    if (i < n * 3)  g_delta[i] = 0.f;
    if (i < n)      g_deg[i] = 0.f;
    if (i < 16384) {
        int j = i >> 7, k = i & 127;
        g_Bh[j * 128 + k]  = __half_as_ushort(__float2half_rn(ew2[k * 128 + j]));
        g_Bd[j * 128 + k]  = __half_as_ushort(__float2half_rn(ew1[k * 128 + j]));
        g_Bs[j * 128 + k]  = __half_as_ushort(__float2half_rn(ew1[(128 + k) * 128 + j]));
        g_Bn2[j * 128 + k] = __half_as_ushort(__float2half_rn(nw2[k * 128 + j]));
    }
    if (i < 32768) {
        int j = i >> 8, k = i & 255;        // [128][256]
        g_Bn1[j * 256 + k] = __half_as_ushort(__float2half_rn(nw1[k * 128 + j]));
    }
}

// ---------------- HMMA proj kernel: P1h, P2h --------------------------------
#define PK_EB1  0
#define PK_A    1024
#define PK_BD   (PK_A + TILE_B)
#define PK_BS   (PK_BD + TILE_B)
#define PROJ_SMEM_BYTES (PK_BS + TILE_B)   // 105472

__global__ __launch_bounds__(512, 2) void proj_hmma(
    const float* __restrict__ h, const float* __restrict__ eb1, int N)
{
    char* smem = smem_raw;
    const uint32_t sb = (uint32_t)__cvta_generic_to_shared(smem);
    float* s_eb1 = (float*)(smem + PK_EB1);
    const int tid = threadIdx.x, wid = tid >> 5, lane = tid & 31;
    const int n0 = blockIdx.x * 128;

    if (tid < 32) *(float4*)(s_eb1 + tid * 4) = __ldg((const float4*)eb1 + tid);
    for (int i = tid; i < 128 * 16; i += 512) {
        int rw = i >> 4, c = i & 15;
        *(uint4*)(smem + PK_BD + rw * AROWB + c * 16) = ((const uint4*)g_Bd)[rw * 16 + c];
        *(uint4*)(smem + PK_BS + rw * AROWB + c * 16) = ((const uint4*)g_Bs)[rw * 16 + c];
    }
#pragma unroll
    for (int it = 0; it < 8; it++) {
        int row = wid * 8 + it;
        int n = n0 + row;
        float4 v = make_float4(0.f, 0.f, 0.f, 0.f);
        if (n < N) v = __ldg((const float4*)h + (size_t)n * 32 + lane);
        __half2 h01 = __floats2half2_rn(v.x, v.y);
        __half2 h23 = __floats2half2_rn(v.z, v.w);
        uint2 u; u.x = *(uint32_t*)&h01; u.y = *(uint32_t*)&h23;
        *(uint2*)(smem + PK_A + row * AROWB + lane * 8) = u;
    }
    __syncthreads();

    const int mw = wid & 7, nw = wid >> 3;   // 8 M-warps x 2 N-warps
    const int mi = lane >> 3, r = lane & 7;
    const uint32_t aBase = sb + PK_A
        + (uint32_t)((mw * 16 + (mi & 1) * 8 + r) * APITCH + (mi >> 1) * 8) * 2u;
    const uint32_t bBase = sb + PK_BD
        + (uint32_t)((nw * 64 + (mi >> 1) * 8 + r) * APITCH + (mi & 1) * 8) * 2u;
    const int gid = lane >> 2, tig = lane & 3;

    uint32_t c[8][2];
#pragma unroll
    for (int pass = 0; pass < 2; pass++) {
#pragma unroll
        for (int nt = 0; nt < 8; nt++) { c[nt][0] = 0u; c[nt][1] = 0u; }
        uint32_t bb = bBase + pass * (PK_BS - PK_BD);
#pragma unroll
        for (int ks = 0; ks < 8; ks++) {
            uint32_t af[4];
            LDSM_X4(af, aBase + ks * 32);
            uint32_t kb = bb + ks * 32;
#pragma unroll
            for (int np = 0; np < 4; np++) {
                uint32_t bf[4];
                LDSM_X4(bf, kb);
                mma16816h(c[2*np],   af, bf + 0);
                mma16816h(c[2*np+1], af, bf + 2);
                kb += 16 * AROWB;
            }
        }
        unsigned short* dst = pass == 0 ? g_P1h : g_P2h;
        int rA = mw * 16 + gid;
        int nA = n0 + rA, nB = nA + 8;
#pragma unroll
        for (int nt = 0; nt < 8; nt++) {
            int col = nw * 64 + nt * 8 + tig * 2;
            float b0 = pass == 0 ? s_eb1[col] : 0.f;
            float b1 = pass == 0 ? s_eb1[col + 1] : 0.f;
            float2 vA = h2f2(c[nt][0]);
            float2 vB = h2f2(c[nt][1]);
            if (nA < N)
                *(__half2*)(dst + (size_t)nA * 128 + col) =
                    __floats2half2_rn(vA.x + b0, vA.y + b1);
            if (nB < N)
                *(__half2*)(dst + (size_t)nB * 128 + col) =
                    __floats2half2_rn(vB.x + b0, vB.y + b1);
        }
    }
}

// ---------------- HMMA edge kernel ------------------------------------------
#define EK_DST   0
#define EK_SRC   512
#define EK_DSQ   1024
#define EK_DIST  1536
#define EK_REL   2048
#define EK_EA    3584
#define EK_TAIL  5632
#define EK_EB2   8192
#define EK_A     8704
#define EK_B     (EK_A + TILE_B)
#define EK_MSG   EK_A
#define EDGE_SMEM_BYTES (EK_B + TILE_B)   // 78336

__global__ __launch_bounds__(512, 2) void edge_tc_kernel(
    const float* __restrict__ x,
    const void*  __restrict__ eidx, const float* __restrict__ eattr,
    const float* __restrict__ ew1, const float* __restrict__ eb2,
    const float* __restrict__ cw1, const float* __restrict__ cb1,
    const float* __restrict__ cw2, const float* __restrict__ cb2,
    int E)
{
    char* smem = smem_raw;
    const uint32_t sb = (uint32_t)__cvta_generic_to_shared(smem);
    int*   s_dst  = (int*)(smem + EK_DST);
    int*   s_src  = (int*)(smem + EK_SRC);
    float* s_dsq  = (float*)(smem + EK_DSQ);
    float* s_dist = (float*)(smem + EK_DIST);
    float* s_rel  = (float*)(smem + EK_REL);
    float* s_ea   = (float*)(smem + EK_EA);
    float* s_tail = (float*)(smem + EK_TAIL);
    float* s_eb2  = (float*)(smem + EK_EB2);

    const int tid  = threadIdx.x;
    const int wid  = tid >> 5;
    const int lane = tid & 31;
    const int e0   = blockIdx.x * 128;

    if (tid < 128) {
        int ge = e0 + tid;
        int dI = -1, sI = 0;
        float rx = 0.f, ry = 0.f, rz = 0.f, dsq = 1e-8f;
        float4 ea = make_float4(0.f, 0.f, 0.f, 0.f);
        if (ge < E) {
            if (g_is64) {
                const long long* p = (const long long*)eidx;
                sI = (int)p[ge]; dI = (int)p[E + ge];
            } else {
                const int* p = (const int*)eidx;
                sI = p[ge]; dI = p[E + ge];
            }
            const float* xd = x + (size_t)dI * 3;
            const float* xs = x + (size_t)sI * 3;
            rx = xd[0] - xs[0]; ry = xd[1] - xs[1]; rz = xd[2] - xs[2];
            dsq = fmaxf(rx * rx + ry * ry + rz * rz, 1e-8f);
            ea = ((const float4*)eattr)[ge];
        }
        s_dst[tid] = dI; s_src[tid] = sI;
        s_rel[tid * 3 + 0] = rx; s_rel[tid * 3 + 1] = ry; s_rel[tid * 3 + 2] = rz;
        s_dist[tid] = sqrtf(dsq);
        s_dsq[tid]  = dsq;
        *(float4*)(s_ea + tid * 4) = ea;
    }
    if (tid >= 128 && tid < 288) {
        int t = tid - 128;
        int r = t >> 5, c = t & 31;
        *(float4*)(s_tail + r * 128 + c * 4) =
            __ldg((const float4*)(ew1 + (256 + r) * 128) + c);
    }
    if (tid >= 288 && tid < 320)
        *(float4*)(s_eb2 + (tid - 288) * 4) = __ldg((const float4*)eb2 + (tid - 288));
    for (int i = tid; i < 128 * 16; i += 512) {
        int rw = i >> 4, c = i & 15;
        *(uint4*)(smem + EK_B + rw * AROWB + c * 16) = ((const uint4*)g_Bh)[rw * 16 + c];
    }
    __syncthreads();

    // ---- gather fp16 P1/P2 + tail + silu -> fp16 A tile (8 edges/warp) ----
#pragma unroll
    for (int it = 0; it < 8; it++) {
        int e  = wid * 8 + it;
        int dI = s_dst[e];
        float4 v = make_float4(0.f, 0.f, 0.f, 0.f);
        if (dI >= 0) {
            uint2 ua = *(const uint2*)(g_P1h + (size_t)dI * 128 + lane * 4);
            uint2 ub = *(const uint2*)(g_P2h + (size_t)s_src[e] * 128 + lane * 4);
            __half2 a01 = *(__half2*)&ua.x, a23 = *(__half2*)&ua.y;
            __half2 b01 = *(__half2*)&ub.x, b23 = *(__half2*)&ub.y;
            float ds = s_dsq[e];
            float4 ea = *(const float4*)(s_ea + e * 4);
            float4 wd = *(const float4*)(s_tail + 0 * 128 + lane * 4);
            float4 a0 = *(const float4*)(s_tail + 1 * 128 + lane * 4);
            float4 a1 = *(const float4*)(s_tail + 2 * 128 + lane * 4);
            float4 a2 = *(const float4*)(s_tail + 3 * 128 + lane * 4);
            float4 a3 = *(const float4*)(s_tail + 4 * 128 + lane * 4);
            v.x = __low2float(a01)  + __low2float(b01)
                + fmaf(ds,wd.x,fmaf(ea.x,a0.x,fmaf(ea.y,a1.x,fmaf(ea.z,a2.x,ea.w*a3.x))));
            v.y = __high2float(a01) + __high2float(b01)
                + fmaf(ds,wd.y,fmaf(ea.x,a0.y,fmaf(ea.y,a1.y,fmaf(ea.z,a2.y,ea.w*a3.y))));
            v.z = __low2float(a23)  + __low2float(b23)
                + fmaf(ds,wd.z,fmaf(ea.x,a0.z,fmaf(ea.y,a1.z,fmaf(ea.z,a2.z,ea.w*a3.z))));
            v.w = __high2float(a23) + __high2float(b23)
                + fmaf(ds,wd.w,fmaf(ea.x,a0.w,fmaf(ea.y,a1.w,fmaf(ea.z,a2.w,ea.w*a3.w))));
            v.x = silu_f(v.x); v.y = silu_f(v.y); v.z = silu_f(v.z); v.w = silu_f(v.w);
        }
        __half2 h01 = __floats2half2_rn(v.x, v.y);
        __half2 h23 = __floats2half2_rn(v.z, v.w);
        uint2 u; u.x = *(uint32_t*)&h01; u.y = *(uint32_t*)&h23;
        *(uint2*)(smem + EK_A + e * AROWB + lane * 8) = u;
    }
    __syncthreads();

    // ---- fp16 HMMA (f16 accum), each warp D[16 x 64] ----
    const int mw = wid & 7;
    const int nw = wid >> 3;
    uint32_t c[8][2];
#pragma unroll
    for (int nt = 0; nt < 8; nt++) { c[nt][0] = 0u; c[nt][1] = 0u; }
    {
        const int mi = lane >> 3, r = lane & 7;
        uint32_t aBase = sb + EK_A
            + (uint32_t)((mw * 16 + (mi & 1) * 8 + r) * APITCH + (mi >> 1) * 8) * 2u;
        uint32_t bBase = sb + EK_B
            + (uint32_t)((nw * 64 + (mi >> 1) * 8 + r) * APITCH + (mi & 1) * 8) * 2u;
#pragma unroll
        for (int ks = 0; ks < 8; ks++) {
            uint32_t af[4];
            LDSM_X4(af, aBase + ks * 32);
            uint32_t kb = bBase + ks * 32;
#pragma unroll
            for (int np = 0; np < 4; np++) {
                uint32_t bf[4];
                LDSM_X4(bf, kb);
                mma16816h(c[2*np],   af, bf + 0);
                mma16816h(c[2*np+1], af, bf + 2);
                kb += 16 * AROWB;
            }
        }
    }

    // ---- bias + silu; pair-shuffle v4 reductions into g_agg ----
    const int gid = lane >> 2, tig = lane & 3;
    const int skip = g_skip_coord;
    {
        int rA = mw * 16 + gid;
        int rB = rA + 8;
        int dA = s_dst[rA], dB = s_dst[rB];
#pragma unroll
        for (int nt = 0; nt < 8; nt++) {
            int col = nw * 64 + nt * 8 + tig * 2;
            float b0 = s_eb2[col], b1 = s_eb2[col + 1];
            float2 vA = h2f2(c[nt][0]);
            float2 vB = h2f2(c[nt][1]);
            float mA0 = silu_f(vA.x + b0), mA1 = silu_f(vA.y + b1);
            float mB0 = silu_f(vB.x + b0), mB1 = silu_f(vB.y + b1);
            float pA0 = __shfl_down_sync(0xffffffffu, mA0, 1);
            float pA1 = __shfl_down_sync(0xffffffffu, mA1, 1);
            float pB0 = __shfl_down_sync(0xffffffffu, mB0, 1);
            float pB1 = __shfl_down_sync(0xffffffffu, mB1, 1);
            if ((tig & 1) == 0) {
                if (dA >= 0)
                    red_add_v4(g_agg + (size_t)dA * 128 + col, mA0, mA1, pA0, pA1);
                if (dB >= 0)
                    red_add_v4(g_agg + (size_t)dB * 128 + col, mB0, mB1, pB0, pB1);
            }
        }
    }

    if (skip) return;

    // ---- fallback coord path ----
    __syncthreads();
    {
        float* s_msg = (float*)(smem + EK_MSG);
        int rA = mw * 16 + gid;
        int rB = rA + 8;
#pragma unroll
        for (int nt = 0; nt < 8; nt++) {
            int col = nw * 64 + nt * 8 + tig * 2;
            float b0 = s_eb2[col], b1 = s_eb2[col + 1];
            float2 vA = h2f2(c[nt][0]);
            float2 vB = h2f2(c[nt][1]);
            *(float2*)(s_msg + rA * 128 + col) =
                make_float2(silu_f(vA.x + b0), silu_f(vA.y + b1));
            *(float2*)(s_msg + rB * 128 + col) =
                make_float2(silu_f(vB.x + b0), silu_f(vB.y + b1));
        }
    }
    __syncthreads();
    {
        float* s_msg = (float*)(smem + EK_MSG);
        const int jc = tid & 15;
        const int ec = tid >> 4;   // 32 groups x 4 edges
        float4 acc3[4];
#pragma unroll
        for (int e = 0; e < 4; e++) acc3[e] = make_float4(0.f, 0.f, 0.f, 0.f);
        const float4* C1 = (const float4*)cw1;
        const float* sM = s_msg + ec * 4 * 128;
#pragma unroll 2
        for (int k4 = 0; k4 < 32; k4++) {
            const int kb = k4 * 4;
            float4 w0 = __ldg(C1 + (kb + 0) * 16 + jc);
            float4 w1 = __ldg(C1 + (kb + 1) * 16 + jc);
            float4 w2 = __ldg(C1 + (kb + 2) * 16 + jc);
            float4 w3 = __ldg(C1 + (kb + 3) * 16 + jc);
#pragma unroll
            for (int e = 0; e < 4; e++) {
                float4 a = *(const float4*)(sM + e * 128 + kb);
                acc3[e].x = fmaf(a.x,w0.x,fmaf(a.y,w1.x,fmaf(a.z,w2.x,fmaf(a.w,w3.x,acc3[e].x))));
                acc3[e].y = fmaf(a.x,w0.y,fmaf(a.y,w1.y,fmaf(a.z,w2.y,fmaf(a.w,w3.y,acc3[e].y))));
                acc3[e].z = fmaf(a.x,w0.z,fmaf(a.y,w1.z,fmaf(a.z,w2.z,fmaf(a.w,w3.z,acc3[e].z))));
                acc3[e].w = fmaf(a.x,w0.w,fmaf(a.y,w1.w,fmaf(a.z,w2.w,fmaf(a.w,w3.w,acc3[e].w))));
            }
        }
        float4 bc = __ldg((const float4*)cb1 + jc);
        float4 c2 = __ldg((const float4*)cw2 + jc);
        float part[4];
#pragma unroll
        for (int e = 0; e < 4; e++) {
            float cx = silu_f(acc3[e].x + bc.x);
            float cy = silu_f(acc3[e].y + bc.y);
            float cz = silu_f(acc3[e].z + bc.z);
            float cw_ = silu_f(acc3[e].w + bc.w);
            part[e] = cx * c2.x + cy * c2.y + cz * c2.z + cw_ * c2.w;
        }
#pragma unroll
        for (int off = 8; off > 0; off >>= 1) {
#pragma unroll
            for (int e = 0; e < 4; e++)
                part[e] += __shfl_xor_sync(0xffffffffu, part[e], off, 16);
        }
        if (jc == 0) {
            float cb2v = __ldg(cb2);
#pragma unroll
            for (int e = 0; e < 4; e++) {
                int ee = ec * 4 + e;
                int dI = s_dst[ee];
                if (dI >= 0) {
                    float wv = part[e] + cb2v;
                    float f = wv / (s_dist[ee] + 1.f);
                    atomicAdd(&g_delta[dI * 3 + 0], s_rel[ee * 3 + 0] * f);
                    atomicAdd(&g_delta[dI * 3 + 1], s_rel[ee * 3 + 1] * f);
                    atomicAdd(&g_delta[dI * 3 + 2], s_rel[ee * 3 + 2] * f);
                    atomicAdd(&g_deg[dI], 1.f);
                }
            }
        }
    }
}

// ---------------- HMMA node kernel (+ fused coord output) --------------------
#define NK_NB1   0
#define NK_NB2   512
#define NK_LNG   1024
#define NK_LNB   1536
#define NK_A     2048
#define NK_B0    (NK_A + TILE_B)
#define NK_B1    (NK_B0 + TILE_B)
#define NK_O     2048
#define NODE_SMEM_BYTES (NK_B1 + TILE_B)   // 106496

__global__ __launch_bounds__(512, 2) void node_hmma(
    const float* __restrict__ h, const float* __restrict__ x,
    const float* __restrict__ nb1, const float* __restrict__ nb2,
    const float* __restrict__ ln_g, const float* __restrict__ ln_b,
    const float* __restrict__ logit,
    float* __restrict__ out, float* __restrict__ out_x, int N)
{
    char* smem = smem_raw;
    const uint32_t sb = (uint32_t)__cvta_generic_to_shared(smem);
    float* s_nb1 = (float*)(smem + NK_NB1);
    float* s_nb2 = (float*)(smem + NK_NB2);
    float* s_lng = (float*)(smem + NK_LNG);
    float* s_lnb = (float*)(smem + NK_LNB);
    const int tid = threadIdx.x, wid = tid >> 5, lane = tid & 31;
    const int n0 = blockIdx.x * 128;

    // fused coord output (inputs final before this kernel launches)
    if (tid < 128) {
        int n = n0 + tid;
        if (n < N) {
            if (g_skip_coord) {
                out_x[n * 3 + 0] = x[n * 3 + 0];
                out_x[n * 3 + 1] = x[n * 3 + 1];
                out_x[n * 3 + 2] = x[n * 3 + 2];
            } else {
                float scale = 1.f / (1.f + expf(-logit[0]));
                float dg = fmaxf(g_deg[n], 1.f);
                float inv = scale / dg;
                out_x[n * 3 + 0] = x[n * 3 + 0] + g_delta[n * 3 + 0] * inv;
                out_x[n * 3 + 1] = x[n * 3 + 1] + g_delta[n * 3 + 1] * inv;
                out_x[n * 3 + 2] = x[n * 3 + 2] + g_delta[n * 3 + 2] * inv;
            }
        }
    }

    if (tid >= 448 && tid < 480) {
        int t = tid - 448;
        *(float4*)(s_nb1 + t * 4) = __ldg((const float4*)nb1 + t);
        *(float4*)(s_nb2 + t * 4) = __ldg((const float4*)nb2 + t);
        *(float4*)(s_lng + t * 4) = __ldg((const float4*)ln_g + t);
        *(float4*)(s_lnb + t * 4) = __ldg((const float4*)ln_b + t);
    }
    for (int i = tid; i < 128 * 16; i += 512) {
        int rw = i >> 4, c = i & 15;
        *(uint4*)(smem + NK_B0 + rw * AROWB + c * 16) = ((const uint4*)g_Bn1)[rw * 32 + c];
        *(uint4*)(smem + NK_B1 + rw * AROWB + c * 16) = ((const uint4*)g_Bn1)[rw * 32 + 16 + c];
    }
#pragma unroll
    for (int it = 0; it < 8; it++) {
        int row = wid * 8 + it;
        int n = n0 + row;
        float4 v = make_float4(0.f, 0.f, 0.f, 0.f);
        if (n < N) v = __ldg((const float4*)h + (size_t)n * 32 + lane);
        __half2 h01 = __floats2half2_rn(v.x, v.y);
        __half2 h23 = __floats2half2_rn(v.z, v.w);
        uint2 u; u.x = *(uint32_t*)&h01; u.y = *(uint32_t*)&h23;
        *(uint2*)(smem + NK_A + row * AROWB + lane * 8) = u;
    }
    __syncthreads();

    const int mw = wid & 7, nw = wid >> 3;
    const int mi = lane >> 3, r = lane & 7;
    const uint32_t aBase = sb + NK_A
        + (uint32_t)((mw * 16 + (mi & 1) * 8 + r) * APITCH + (mi >> 1) * 8) * 2u;
    const uint32_t bBase0 = sb + NK_B0
        + (uint32_t)((nw * 64 + (mi >> 1) * 8 + r) * APITCH + (mi & 1) * 8) * 2u;
    const int gid = lane >> 2, tig = lane & 3;

    uint32_t c[8][2];
#pragma unroll
    for (int nt = 0; nt < 8; nt++) { c[nt][0] = 0u; c[nt][1] = 0u; }

    // layer 1, k-half 0 (A = h fp16)
#pragma unroll
    for (int ks = 0; ks < 8; ks++) {
        uint32_t af[4];
        LDSM_X4(af, aBase + ks * 32);
        uint32_t kb = bBase0 + ks * 32;
#pragma unroll
        for (int np = 0; np < 4; np++) {
            uint32_t bf[4];
            LDSM_X4(bf, kb);
            mma16816h(c[2*np],   af, bf + 0);
            mma16816h(c[2*np+1], af, bf + 2);
            kb += 16 * AROWB;
        }
    }
    __syncthreads();
#pragma unroll
    for (int it = 0; it < 8; it++) {
        int row = wid * 8 + it;
        int n = n0 + row;
        float4 v = make_float4(0.f, 0.f, 0.f, 0.f);
        if (n < N) v = *((const float4*)g_agg + (size_t)n * 32 + lane);
        __half2 h01 = __floats2half2_rn(v.x, v.y);
        __half2 h23 = __floats2half2_rn(v.z, v.w);
        uint2 u; u.x = *(uint32_t*)&h01; u.y = *(uint32_t*)&h23;
        *(uint2*)(smem + NK_A + row * AROWB + lane * 8) = u;
    }
    __syncthreads();
    // layer 1, k-half 1 (A = agg)
#pragma unroll
    for (int ks = 0; ks < 8; ks++) {
        uint32_t af[4];
        LDSM_X4(af, aBase + ks * 32);
        uint32_t kb = bBase0 + (NK_B1 - NK_B0) + ks * 32;
#pragma unroll
        for (int np = 0; np < 4; np++) {
            uint32_t bf[4];
            LDSM_X4(bf, kb);
            mma16816h(c[2*np],   af, bf + 0);
            mma16816h(c[2*np+1], af, bf + 2);
            kb += 16 * AROWB;
        }
    }
    __syncthreads();
    // t1 = silu(c + nb1) -> fp16 into NK_A; Bn2 -> NK_B0
    {
        int rA = mw * 16 + gid;
        int rB = rA + 8;
#pragma unroll
        for (int nt = 0; nt < 8; nt++) {
            int col = nw * 64 + nt * 8 + tig * 2;
            float b0 = s_nb1[col], b1 = s_nb1[col + 1];
            float2 vA = h2f2(c[nt][0]);
            float2 vB = h2f2(c[nt][1]);
            *(__half2*)(smem + NK_A + rA * AROWB + col * 2) =
                __floats2half2_rn(silu_f(vA.x + b0), silu_f(vA.y + b1));
            *(__half2*)(smem + NK_A + rB * AROWB + col * 2) =
                __floats2half2_rn(silu_f(vB.x + b0), silu_f(vB.y + b1));
        }
    }
    for (int i = tid; i < 128 * 16; i += 512) {
        int rw = i >> 4, cc = i & 15;
        *(uint4*)(smem + NK_B0 + rw * AROWB + cc * 16) = ((const uint4*)g_Bn2)[rw * 16 + cc];
    }
    __syncthreads();

    // layer 2
#pragma unroll
    for (int nt = 0; nt < 8; nt++) { c[nt][0] = 0u; c[nt][1] = 0u; }
#pragma unroll
    for (int ks = 0; ks < 8; ks++) {
        uint32_t af[4];
        LDSM_X4(af, aBase + ks * 32);
        uint32_t kb = bBase0 + ks * 32;
#pragma unroll
        for (int np = 0; np < 4; np++) {
            uint32_t bf[4];
            LDSM_X4(bf, kb);
            mma16816h(c[2*np],   af, bf + 0);
            mma16816h(c[2*np+1], af, bf + 2);
            kb += 16 * AROWB;
        }
    }
    __syncthreads();
    // stage o = c + nb2 + h (residual) fp32 into NK_O (pitch 132)
    {
        float* s_o = (float*)(smem + NK_O);
        int rA = mw * 16 + gid;
        int rB = rA + 8;
        int nA = n0 + rA, nB = n0 + rB;
#pragma unroll
        for (int nt = 0; nt < 8; nt++) {
            int col = nw * 64 + nt * 8 + tig * 2;
            float b0 = s_nb2[col], b1 = s_nb2[col + 1];
            float2 hA = make_float2(0.f, 0.f), hB = make_float2(0.f, 0.f);
            if (nA < N) hA = *(const float2*)(h + (size_t)nA * 128 + col);
            if (nB < N) hB = *(const float2*)(h + (size_t)nB * 128 + col);
            float2 vA = h2f2(c[nt][0]);
            float2 vB = h2f2(c[nt][1]);
            *(float2*)(s_o + rA * 132 + col) =
                make_float2(vA.x + b0 + hA.x, vA.y + b1 + hA.y);
            *(float2*)(s_o + rB * 132 + col) =
                make_float2(vB.x + b0 + hB.x, vB.y + b1 + hB.y);
        }
    }
    __syncthreads();
    // LayerNorm per row, write out
    {
        float* s_o = (float*)(smem + NK_O);
#pragma unroll
        for (int it = 0; it < 8; it++) {
            int row = wid * 8 + it;
            int n = n0 + row;
            float4 o = *(const float4*)(s_o + row * 132 + lane * 4);
            float s = o.x + o.y + o.z + o.w;
#pragma unroll
            for (int off = 16; off > 0; off >>= 1)
                s += __shfl_xor_sync(0xffffffffu, s, off);
            float mean = s * (1.f / 128.f);
            float dx = o.x - mean, dy = o.y - mean, dz = o.z - mean, dw = o.w - mean;
            float q = dx * dx + dy * dy + dz * dz + dw * dw;
#pragma unroll
            for (int off = 16; off > 0; off >>= 1)
                q += __shfl_xor_sync(0xffffffffu, q, off);
            float inv = rsqrtf(q * (1.f / 128.f) + 1e-5f);
            float4 g4 = *(const float4*)(s_lng + lane * 4);
            float4 bb = *(const float4*)(s_lnb + lane * 4);
            float4 y;
            y.x = dx * inv * g4.x + bb.x;
            y.y = dy * inv * g4.y + bb.y;
            y.z = dz * inv * g4.z + bb.z;
            y.w = dw * inv * g4.w + bb.w;
            if (n < N) ((float4*)out)[(size_t)n * 32 + lane] = y;
        }
    }
}

// ---------------- launcher ----------------------------------------------------
extern "C" void kernel_launch(void* const* d_in, const int* in_sizes, int n_in,
                              void* d_out, int out_size)
{
    const float* h   = (const float*)d_in[0];
    const float* x   = (const float*)d_in[1];
    const void*  ei  = d_in[2];
    const float* ea  = (const float*)d_in[3];
    const float* ew1 = (const float*)d_in[4];
    const float* eb1 = (const float*)d_in[5];
    const float* ew2 = (const float*)d_in[6];
    const float* eb2 = (const float*)d_in[7];
    const float* nw1 = (const float*)d_in[8];
    const float* nb1 = (const float*)d_in[9];
    const float* nw2 = (const float*)d_in[10];
    const float* nb2 = (const float*)d_in[11];
    const float* cw1 = (const float*)d_in[12];
    const float* cb1 = (const float*)d_in[13];
    const float* cw2 = (const float*)d_in[14];
    const float* cb2 = (const float*)d_in[15];
    const float* lgt = (const float*)d_in[16];
    const float* lng = (const float*)d_in[17];
    const float* lnb = (const float*)d_in[18];

    const int N = in_sizes[0] / 128;
    const int E = in_sizes[3] / 4;

    float* out_h = (float*)d_out;
    float* out_x = out_h + (size_t)N * 128;

    cudaFuncSetAttribute(proj_hmma, cudaFuncAttributeMaxDynamicSharedMemorySize,
                         PROJ_SMEM_BYTES);
    cudaFuncSetAttribute(edge_tc_kernel, cudaFuncAttributeMaxDynamicSharedMemorySize,
                         EDGE_SMEM_BYTES);
    cudaFuncSetAttribute(node_hmma, cudaFuncAttributeMaxDynamicSharedMemorySize,
                         NODE_SMEM_BYTES);

    setup_kernel<<<(N * 32 + 511) / 512, 512>>>(
        (const unsigned int*)ei, cw2, cb2, ew2, ew1, nw1, nw2, N);
    proj_hmma<<<(N + 127) / 128, 512, PROJ_SMEM_BYTES>>>(h, eb1, N);
    edge_tc_kernel<<<(E + 127) / 128, 512, EDGE_SMEM_BYTES>>>(
        x, ei, ea, ew1, eb2, cw1, cb1, cw2, cb2, E);
    node_hmma<<<(N + 127) / 128, 512, NODE_SMEM_BYTES>>>(
        h, x, nb1, nb2, lng, lnb, lgt, out_h, out_x, N);
}

// round 15
// speedup vs baseline: 1.1287x; 1.0082x over previous
#include <cuda_runtime.h>
#include <cuda_bf16.h>
#include <cuda_fp16.h>
#include <cstdint>

#define NMAX 50000

extern __shared__ __align__(1024) char smem_raw[];

// ---------------- scratch ----------------------------------------------------
__device__ float g_agg[NMAX * 128];
__device__ __align__(16) unsigned short g_P1h[NMAX * 128];  // fp16: h@W_d + eb1
__device__ __align__(16) unsigned short g_P2h[NMAX * 128];  // fp16: h@W_s
__device__ float g_delta[NMAX * 3];
__device__ float g_deg[NMAX];
__device__ int   g_is64;
__device__ int   g_skip_coord;
// fp16 weight images, row-major [out n][in k]
__device__ __align__(16) unsigned short g_Bh[16384];    // ew2^T
__device__ __align__(16) unsigned short g_Bd[16384];    // ew1[0:128]^T
__device__ __align__(16) unsigned short g_Bs[16384];    // ew1[128:256]^T
__device__ __align__(16) unsigned short g_Bn1[32768];   // nw1^T [128][256]
__device__ __align__(16) unsigned short g_Bn2[16384];   // nw2^T [128][128]

__device__ __forceinline__ float silu_f(float v) { return v / (1.f + __expf(-v)); }

// ---------------- ptx helpers ----------------------------------------------
#define LDSM_X4(r, addr) \
    asm volatile("ldmatrix.sync.aligned.m8n8.x4.shared.b16 {%0,%1,%2,%3}, [%4];" \
        : "=r"((r)[0]), "=r"((r)[1]), "=r"((r)[2]), "=r"((r)[3]) : "r"(addr))

// fp16-accumulate HMMA: D/C are 2 packed half2 regs.
__device__ __forceinline__ void mma16816h(uint32_t* d, const uint32_t* a, const uint32_t* b) {
    asm volatile("mma.sync.aligned.m16n8k16.row.col.f16.f16.f16.f16 "
        "{%0,%1}, {%2,%3,%4,%5}, {%6,%7}, {%0,%1};"
        : "+r"(d[0]), "+r"(d[1])
        : "r"(a[0]), "r"(a[1]), "r"(a[2]), "r"(a[3]), "r"(b[0]), "r"(b[1]));
}

__device__ __forceinline__ void red_add_v4(float* p, float a, float b, float c, float d) {
    asm volatile("red.global.add.v4.f32 [%0], {%1, %2, %3, %4};"
        :: "l"(p), "f"(a), "f"(b), "f"(c), "f"(d) : "memory");
}

__device__ __forceinline__ float2 h2f2(uint32_t u) {
    __half2 h = *(__half2*)&u;
    return __half22float2(h);
}

#define APITCH  136
#define AROWB   272
#define TILE_B  (128 * AROWB)        // 34816 bytes per fp16 tile

// ---------------- fused setup kernel -----------------------------------------
__global__ void setup_kernel(const unsigned int* __restrict__ w,
                             const float* __restrict__ cw2,
                             const float* __restrict__ cb2,
                             const float* __restrict__ ew2,
                             const float* __restrict__ ew1,
                             const float* __restrict__ nw1,
                             const float* __restrict__ nw2,
                             int n)
{
    int i = blockIdx.x * blockDim.x + threadIdx.x;
    if (i == 0) {
        int all0 = 1;
#pragma unroll
        for (int k = 1; k < 64; k += 2) all0 &= (w[k] == 0u);
        g_is64 = all0;
        int z = (cb2[0] == 0.f);
        for (int k = 0; k < 64; k++) z &= (cw2[k] == 0.f);
        g_skip_coord = z;
    }
    float4 z4 = make_float4(0.f, 0.f, 0.f, 0.f);
    if (i < n * 32) ((float4*)g_agg)[i] = z4;
    if (i < n * 3)  g_delta[i] = 0.f;
    if (i < n)      g_deg[i] = 0.f;
    if (i < 16384) {
        int j = i >> 7, k = i & 127;
        g_Bh[j * 128 + k]  = __half_as_ushort(__float2half_rn(ew2[k * 128 + j]));
        g_Bd[j * 128 + k]  = __half_as_ushort(__float2half_rn(ew1[k * 128 + j]));
        g_Bs[j * 128 + k]  = __half_as_ushort(__float2half_rn(ew1[(128 + k) * 128 + j]));
        g_Bn2[j * 128 + k] = __half_as_ushort(__float2half_rn(nw2[k * 128 + j]));
    }
    if (i < 32768) {
        int j = i >> 8, k = i & 255;        // [128][256]
        g_Bn1[j * 256 + k] = __half_as_ushort(__float2half_rn(nw1[k * 128 + j]));
    }
}

// ---------------- HMMA proj kernel: P1h, P2h --------------------------------
#define PK_EB1  0
#define PK_A    1024
#define PK_BD   (PK_A + TILE_B)
#define PK_BS   (PK_BD + TILE_B)
#define PROJ_SMEM_BYTES (PK_BS + TILE_B)   // 105472

__global__ __launch_bounds__(512, 2) void proj_hmma(
    const float* __restrict__ h, const float* __restrict__ eb1, int N)
{
    char* smem = smem_raw;
    const uint32_t sb = (uint32_t)__cvta_generic_to_shared(smem);
    float* s_eb1 = (float*)(smem + PK_EB1);
    const int tid = threadIdx.x, wid = tid >> 5, lane = tid & 31;
    const int n0 = blockIdx.x * 128;

    if (tid < 32) *(float4*)(s_eb1 + tid * 4) = __ldg((const float4*)eb1 + tid);
    for (int i = tid; i < 128 * 16; i += 512) {
        int rw = i >> 4, c = i & 15;
        *(uint4*)(smem + PK_BD + rw * AROWB + c * 16) = ((const uint4*)g_Bd)[rw * 16 + c];
        *(uint4*)(smem + PK_BS + rw * AROWB + c * 16) = ((const uint4*)g_Bs)[rw * 16 + c];
    }
#pragma unroll
    for (int it = 0; it < 8; it++) {
        int row = wid * 8 + it;
        int n = n0 + row;
        float4 v = make_float4(0.f, 0.f, 0.f, 0.f);
        if (n < N) v = __ldg((const float4*)h + (size_t)n * 32 + lane);
        __half2 h01 = __floats2half2_rn(v.x, v.y);
        __half2 h23 = __floats2half2_rn(v.z, v.w);
        uint2 u; u.x = *(uint32_t*)&h01; u.y = *(uint32_t*)&h23;
        *(uint2*)(smem + PK_A + row * AROWB + lane * 8) = u;
    }
    __syncthreads();

    const int mw = wid & 7, nw = wid >> 3;   // 8 M-warps x 2 N-warps
    const int mi = lane >> 3, r = lane & 7;
    const uint32_t aBase = sb + PK_A
        + (uint32_t)((mw * 16 + (mi & 1) * 8 + r) * APITCH + (mi >> 1) * 8) * 2u;
    const uint32_t bBase = sb + PK_BD
        + (uint32_t)((nw * 64 + (mi >> 1) * 8 + r) * APITCH + (mi & 1) * 8) * 2u;
    const int gid = lane >> 2, tig = lane & 3;

    uint32_t c[8][2];
#pragma unroll
    for (int pass = 0; pass < 2; pass++) {
#pragma unroll
        for (int nt = 0; nt < 8; nt++) { c[nt][0] = 0u; c[nt][1] = 0u; }
        uint32_t bb = bBase + pass * (PK_BS - PK_BD);
#pragma unroll
        for (int ks = 0; ks < 8; ks++) {
            uint32_t af[4];
            LDSM_X4(af, aBase + ks * 32);
            uint32_t kb = bb + ks * 32;
#pragma unroll
            for (int np = 0; np < 4; np++) {
                uint32_t bf[4];
                LDSM_X4(bf, kb);
                mma16816h(c[2*np],   af, bf + 0);
                mma16816h(c[2*np+1], af, bf + 2);
                kb += 16 * AROWB;
            }
        }
        unsigned short* dst = pass == 0 ? g_P1h : g_P2h;
        int rA = mw * 16 + gid;
        int nA = n0 + rA, nB = nA + 8;
#pragma unroll
        for (int nt = 0; nt < 8; nt++) {
            int col = nw * 64 + nt * 8 + tig * 2;
            float b0 = pass == 0 ? s_eb1[col] : 0.f;
            float b1 = pass == 0 ? s_eb1[col + 1] : 0.f;
            float2 vA = h2f2(c[nt][0]);
            float2 vB = h2f2(c[nt][1]);
            if (nA < N)
                *(__half2*)(dst + (size_t)nA * 128 + col) =
                    __floats2half2_rn(vA.x + b0, vA.y + b1);
            if (nB < N)
                *(__half2*)(dst + (size_t)nB * 128 + col) =
                    __floats2half2_rn(vB.x + b0, vB.y + b1);
        }
    }
}

// ---------------- HMMA edge kernel ------------------------------------------
#define EK_DST   0                    // int[128]
#define EK_SRC   512
#define EK_DSQ   1024                 // float[128]
#define EK_REL   1536                 // float[128][3]
#define EK_EA    3072                 // half[128][4]
#define EK_TAIL  4096                 // float[5][128]
#define EK_EB2   6656                 // float[128]
#define EK_A     7168
#define EK_B     (EK_A + TILE_B)      // 41984
#define EK_MSG   EK_A
#define EDGE_SMEM_BYTES (EK_B + TILE_B)   // 76800

__global__ __launch_bounds__(512, 2) void edge_tc_kernel(
    const float* __restrict__ x,
    const void*  __restrict__ eidx, const float* __restrict__ eattr,
    const float* __restrict__ ew1, const float* __restrict__ eb2,
    const float* __restrict__ cw1, const float* __restrict__ cb1,
    const float* __restrict__ cw2, const float* __restrict__ cb2,
    int E)
{
    char* smem = smem_raw;
    const uint32_t sb = (uint32_t)__cvta_generic_to_shared(smem);
    int*    s_dst  = (int*)(smem + EK_DST);
    int*    s_src  = (int*)(smem + EK_SRC);
    float*  s_dsq  = (float*)(smem + EK_DSQ);
    float*  s_rel  = (float*)(smem + EK_REL);
    __half* s_ea   = (__half*)(smem + EK_EA);
    float*  s_tail = (float*)(smem + EK_TAIL);
    float*  s_eb2  = (float*)(smem + EK_EB2);

    const int tid  = threadIdx.x;
    const int wid  = tid >> 5;
    const int lane = tid & 31;
    const int e0   = blockIdx.x * 128;

    if (tid < 128) {
        int ge = e0 + tid;
        int dI = -1, sI = 0;
        float rx = 0.f, ry = 0.f, rz = 0.f, dsq = 1e-8f;
        float4 ea = make_float4(0.f, 0.f, 0.f, 0.f);
        if (ge < E) {
            if (g_is64) {
                const long long* p = (const long long*)eidx;
                sI = (int)p[ge]; dI = (int)p[E + ge];
            } else {
                const int* p = (const int*)eidx;
                sI = p[ge]; dI = p[E + ge];
            }
            const float* xd = x + (size_t)dI * 3;
            const float* xs = x + (size_t)sI * 3;
            rx = xd[0] - xs[0]; ry = xd[1] - xs[1]; rz = xd[2] - xs[2];
            dsq = fmaxf(rx * rx + ry * ry + rz * rz, 1e-8f);
            ea = ((const float4*)eattr)[ge];
        }
        s_dst[tid] = dI; s_src[tid] = sI;
        s_rel[tid * 3 + 0] = rx; s_rel[tid * 3 + 1] = ry; s_rel[tid * 3 + 2] = rz;
        s_dsq[tid] = dsq;
        __half2 e01 = __floats2half2_rn(ea.x, ea.y);
        __half2 e23 = __floats2half2_rn(ea.z, ea.w);
        uint2 u; u.x = *(uint32_t*)&e01; u.y = *(uint32_t*)&e23;
        *(uint2*)(s_ea + tid * 4) = u;
    }
    if (tid >= 128 && tid < 288) {
        int t = tid - 128;
        int r = t >> 5, c = t & 31;
        *(float4*)(s_tail + r * 128 + c * 4) =
            __ldg((const float4*)(ew1 + (256 + r) * 128) + c);
    }
    if (tid >= 288 && tid < 320)
        *(float4*)(s_eb2 + (tid - 288) * 4) = __ldg((const float4*)eb2 + (tid - 288));
    for (int i = tid; i < 128 * 16; i += 512) {
        int rw = i >> 4, c = i & 15;
        *(uint4*)(smem + EK_B + rw * AROWB + c * 16) = ((const uint4*)g_Bh)[rw * 16 + c];
    }
    __syncthreads();

    // ---- gather fp16 P1/P2 + tail + silu -> fp16 A tile (8 edges/warp) ----
#pragma unroll
    for (int it = 0; it < 8; it++) {
        int e  = wid * 8 + it;
        int dI = s_dst[e];
        float4 v = make_float4(0.f, 0.f, 0.f, 0.f);
        if (dI >= 0) {
            uint2 ua = *(const uint2*)(g_P1h + (size_t)dI * 128 + lane * 4);
            uint2 ub = *(const uint2*)(g_P2h + (size_t)s_src[e] * 128 + lane * 4);
            __half2 a01 = *(__half2*)&ua.x, a23 = *(__half2*)&ua.y;
            __half2 b01 = *(__half2*)&ub.x, b23 = *(__half2*)&ub.y;
            float ds = s_dsq[e];
            uint2 ue = *(const uint2*)(s_ea + e * 4);
            float2 e01 = h2f2(ue.x), e23 = h2f2(ue.y);
            float4 ea = make_float4(e01.x, e01.y, e23.x, e23.y);
            float4 wd = *(const float4*)(s_tail + 0 * 128 + lane * 4);
            float4 a0 = *(const float4*)(s_tail + 1 * 128 + lane * 4);
            float4 a1 = *(const float4*)(s_tail + 2 * 128 + lane * 4);
            float4 a2 = *(const float4*)(s_tail + 3 * 128 + lane * 4);
            float4 a3 = *(const float4*)(s_tail + 4 * 128 + lane * 4);
            v.x = __low2float(a01)  + __low2float(b01)
                + fmaf(ds,wd.x,fmaf(ea.x,a0.x,fmaf(ea.y,a1.x,fmaf(ea.z,a2.x,ea.w*a3.x))));
            v.y = __high2float(a01) + __high2float(b01)
                + fmaf(ds,wd.y,fmaf(ea.x,a0.y,fmaf(ea.y,a1.y,fmaf(ea.z,a2.y,ea.w*a3.y))));
            v.z = __low2float(a23)  + __low2float(b23)
                + fmaf(ds,wd.z,fmaf(ea.x,a0.z,fmaf(ea.y,a1.z,fmaf(ea.z,a2.z,ea.w*a3.z))));
            v.w = __high2float(a23) + __high2float(b23)
                + fmaf(ds,wd.w,fmaf(ea.x,a0.w,fmaf(ea.y,a1.w,fmaf(ea.z,a2.w,ea.w*a3.w))));
            v.x = silu_f(v.x); v.y = silu_f(v.y); v.z = silu_f(v.z); v.w = silu_f(v.w);
        }
        __half2 h01 = __floats2half2_rn(v.x, v.y);
        __half2 h23 = __floats2half2_rn(v.z, v.w);
        uint2 u; u.x = *(uint32_t*)&h01; u.y = *(uint32_t*)&h23;
        *(uint2*)(smem + EK_A + e * AROWB + lane * 8) = u;
    }
    __syncthreads();

    // ---- fp16 HMMA (f16 accum), each warp D[16 x 64] ----
    const int mw = wid & 7;
    const int nw = wid >> 3;
    uint32_t c[8][2];
#pragma unroll
    for (int nt = 0; nt < 8; nt++) { c[nt][0] = 0u; c[nt][1] = 0u; }
    {
        const int mi = lane >> 3, r = lane & 7;
        uint32_t aBase = sb + EK_A
            + (uint32_t)((mw * 16 + (mi & 1) * 8 + r) * APITCH + (mi >> 1) * 8) * 2u;
        uint32_t bBase = sb + EK_B
            + (uint32_t)((nw * 64 + (mi >> 1) * 8 + r) * APITCH + (mi & 1) * 8) * 2u;
#pragma unroll
        for (int ks = 0; ks < 8; ks++) {
            uint32_t af[4];
            LDSM_X4(af, aBase + ks * 32);
            uint32_t kb = bBase + ks * 32;
#pragma unroll
            for (int np = 0; np < 4; np++) {
                uint32_t bf[4];
                LDSM_X4(bf, kb);
                mma16816h(c[2*np],   af, bf + 0);
                mma16816h(c[2*np+1], af, bf + 2);
                kb += 16 * AROWB;
            }
        }
    }

    // ---- bias + silu; pair-shuffle v4 reductions into g_agg ----
    const int gid = lane >> 2, tig = lane & 3;
    const int skip = g_skip_coord;
    {
        int rA = mw * 16 + gid;
        int rB = rA + 8;
        int dA = s_dst[rA], dB = s_dst[rB];
#pragma unroll
        for (int nt = 0; nt < 8; nt++) {
            int col = nw * 64 + nt * 8 + tig * 2;
            float b0 = s_eb2[col], b1 = s_eb2[col + 1];
            float2 vA = h2f2(c[nt][0]);
            float2 vB = h2f2(c[nt][1]);
            float mA0 = silu_f(vA.x + b0), mA1 = silu_f(vA.y + b1);
            float mB0 = silu_f(vB.x + b0), mB1 = silu_f(vB.y + b1);
            float pA0 = __shfl_down_sync(0xffffffffu, mA0, 1);
            float pA1 = __shfl_down_sync(0xffffffffu, mA1, 1);
            float pB0 = __shfl_down_sync(0xffffffffu, mB0, 1);
            float pB1 = __shfl_down_sync(0xffffffffu, mB1, 1);
            if ((tig & 1) == 0) {
                if (dA >= 0)
                    red_add_v4(g_agg + (size_t)dA * 128 + col, mA0, mA1, pA0, pA1);
                if (dB >= 0)
                    red_add_v4(g_agg + (size_t)dB * 128 + col, mB0, mB1, pB0, pB1);
            }
        }
    }

    if (skip) return;

    // ---- fallback coord path ----
    __syncthreads();
    {
        float* s_msg = (float*)(smem + EK_MSG);
        int rA = mw * 16 + gid;
        int rB = rA + 8;
#pragma unroll
        for (int nt = 0; nt < 8; nt++) {
            int col = nw * 64 + nt * 8 + tig * 2;
            float b0 = s_eb2[col], b1 = s_eb2[col + 1];
            float2 vA = h2f2(c[nt][0]);
            float2 vB = h2f2(c[nt][1]);
            *(float2*)(s_msg + rA * 128 + col) =
                make_float2(silu_f(vA.x + b0), silu_f(vA.y + b1));
            *(float2*)(s_msg + rB * 128 + col) =
                make_float2(silu_f(vB.x + b0), silu_f(vB.y + b1));
        }
    }
    __syncthreads();
    {
        float* s_msg = (float*)(smem + EK_MSG);
        const int jc = tid & 15;
        const int ec = tid >> 4;   // 32 groups x 4 edges
        float4 acc3[4];
#pragma unroll
        for (int e = 0; e < 4; e++) acc3[e] = make_float4(0.f, 0.f, 0.f, 0.f);
        const float4* C1 = (const float4*)cw1;
        const float* sM = s_msg + ec * 4 * 128;
#pragma unroll 2
        for (int k4 = 0; k4 < 32; k4++) {
            const int kb = k4 * 4;
            float4 w0 = __ldg(C1 + (kb + 0) * 16 + jc);
            float4 w1 = __ldg(C1 + (kb + 1) * 16 + jc);
            float4 w2 = __ldg(C1 + (kb + 2) * 16 + jc);
            float4 w3 = __ldg(C1 + (kb + 3) * 16 + jc);
#pragma unroll
            for (int e = 0; e < 4; e++) {
                float4 a = *(const float4*)(sM + e * 128 + kb);
                acc3[e].x = fmaf(a.x,w0.x,fmaf(a.y,w1.x,fmaf(a.z,w2.x,fmaf(a.w,w3.x,acc3[e].x))));
                acc3[e].y = fmaf(a.x,w0.y,fmaf(a.y,w1.y,fmaf(a.z,w2.y,fmaf(a.w,w3.y,acc3[e].y))));
                acc3[e].z = fmaf(a.x,w0.z,fmaf(a.y,w1.z,fmaf(a.z,w2.z,fmaf(a.w,w3.z,acc3[e].z))));
                acc3[e].w = fmaf(a.x,w0.w,fmaf(a.y,w1.w,fmaf(a.z,w2.w,fmaf(a.w,w3.w,acc3[e].w))));
            }
        }
        float4 bc = __ldg((const float4*)cb1 + jc);
        float4 c2 = __ldg((const float4*)cw2 + jc);
        float part[4];
#pragma unroll
        for (int e = 0; e < 4; e++) {
            float cx = silu_f(acc3[e].x + bc.x);
            float cy = silu_f(acc3[e].y + bc.y);
            float cz = silu_f(acc3[e].z + bc.z);
            float cw_ = silu_f(acc3[e].w + bc.w);
            part[e] = cx * c2.x + cy * c2.y + cz * c2.z + cw_ * c2.w;
        }
#pragma unroll
        for (int off = 8; off > 0; off >>= 1) {
#pragma unroll
            for (int e = 0; e < 4; e++)
                part[e] += __shfl_xor_sync(0xffffffffu, part[e], off, 16);
        }
        if (jc == 0) {
            float cb2v = __ldg(cb2);
#pragma unroll
            for (int e = 0; e < 4; e++) {
                int ee = ec * 4 + e;
                int dI = s_dst[ee];
                if (dI >= 0) {
                    float wv = part[e] + cb2v;
                    float f = wv / (sqrtf(s_dsq[ee]) + 1.f);
                    atomicAdd(&g_delta[dI * 3 + 0], s_rel[ee * 3 + 0] * f);
                    atomicAdd(&g_delta[dI * 3 + 1], s_rel[ee * 3 + 1] * f);
                    atomicAdd(&g_delta[dI * 3 + 2], s_rel[ee * 3 + 2] * f);
                    atomicAdd(&g_deg[dI], 1.f);
                }
            }
        }
    }
}

// ---------------- HMMA node kernel (+ fused coord output) --------------------
#define NK_NB1   0
#define NK_NB2   512
#define NK_LNG   1024
#define NK_LNB   1536
#define NK_A     2048
#define NK_B0    (NK_A + TILE_B)
#define NK_B1    (NK_B0 + TILE_B)
#define NK_O     2048
#define NODE_SMEM_BYTES (NK_B1 + TILE_B)   // 106496

__global__ __launch_bounds__(512, 2) void node_hmma(
    const float* __restrict__ h, const float* __restrict__ x,
    const float* __restrict__ nb1, const float* __restrict__ nb2,
    const float* __restrict__ ln_g, const float* __restrict__ ln_b,
    const float* __restrict__ logit,
    float* __restrict__ out, float* __restrict__ out_x, int N)
{
    char* smem = smem_raw;
    const uint32_t sb = (uint32_t)__cvta_generic_to_shared(smem);
    float* s_nb1 = (float*)(smem + NK_NB1);
    float* s_nb2 = (float*)(smem + NK_NB2);
    float* s_lng = (float*)(smem + NK_LNG);
    float* s_lnb = (float*)(smem + NK_LNB);
    const int tid = threadIdx.x, wid = tid >> 5, lane = tid & 31;
    const int n0 = blockIdx.x * 128;

    // fused coord output (inputs final before this kernel launches)
    if (tid < 128) {
        int n = n0 + tid;
        if (n < N) {
            if (g_skip_coord) {
                out_x[n * 3 + 0] = x[n * 3 + 0];
                out_x[n * 3 + 1] = x[n * 3 + 1];
                out_x[n * 3 + 2] = x[n * 3 + 2];
            } else {
                float scale = 1.f / (1.f + expf(-logit[0]));
                float dg = fmaxf(g_deg[n], 1.f);
                float inv = scale / dg;
                out_x[n * 3 + 0] = x[n * 3 + 0] + g_delta[n * 3 + 0] * inv;
                out_x[n * 3 + 1] = x[n * 3 + 1] + g_delta[n * 3 + 1] * inv;
                out_x[n * 3 + 2] = x[n * 3 + 2] + g_delta[n * 3 + 2] * inv;
            }
        }
    }

    if (tid >= 448 && tid < 480) {
        int t = tid - 448;
        *(float4*)(s_nb1 + t * 4) = __ldg((const float4*)nb1 + t);
        *(float4*)(s_nb2 + t * 4) = __ldg((const float4*)nb2 + t);
        *(float4*)(s_lng + t * 4) = __ldg((const float4*)ln_g + t);
        *(float4*)(s_lnb + t * 4) = __ldg((const float4*)ln_b + t);
    }
    for (int i = tid; i < 128 * 16; i += 512) {
        int rw = i >> 4, c = i & 15;
        *(uint4*)(smem + NK_B0 + rw * AROWB + c * 16) = ((const uint4*)g_Bn1)[rw * 32 + c];
        *(uint4*)(smem + NK_B1 + rw * AROWB + c * 16) = ((const uint4*)g_Bn1)[rw * 32 + 16 + c];
    }
#pragma unroll
    for (int it = 0; it < 8; it++) {
        int row = wid * 8 + it;
        int n = n0 + row;
        float4 v = make_float4(0.f, 0.f, 0.f, 0.f);
        if (n < N) v = __ldg((const float4*)h + (size_t)n * 32 + lane);
        __half2 h01 = __floats2half2_rn(v.x, v.y);
        __half2 h23 = __floats2half2_rn(v.z, v.w);
        uint2 u; u.x = *(uint32_t*)&h01; u.y = *(uint32_t*)&h23;
        *(uint2*)(smem + NK_A + row * AROWB + lane * 8) = u;
    }
    __syncthreads();

    const int mw = wid & 7, nw = wid >> 3;
    const int mi = lane >> 3, r = lane & 7;
    const uint32_t aBase = sb + NK_A
        + (uint32_t)((mw * 16 + (mi & 1) * 8 + r) * APITCH + (mi >> 1) * 8) * 2u;
    const uint32_t bBase0 = sb + NK_B0
        + (uint32_t)((nw * 64 + (mi >> 1) * 8 + r) * APITCH + (mi & 1) * 8) * 2u;
    const int gid = lane >> 2, tig = lane & 3;

    uint32_t c[8][2];
#pragma unroll
    for (int nt = 0; nt < 8; nt++) { c[nt][0] = 0u; c[nt][1] = 0u; }

    // layer 1, k-half 0 (A = h fp16)
#pragma unroll
    for (int ks = 0; ks < 8; ks++) {
        uint32_t af[4];
        LDSM_X4(af, aBase + ks * 32);
        uint32_t kb = bBase0 + ks * 32;
#pragma unroll
        for (int np = 0; np < 4; np++) {
            uint32_t bf[4];
            LDSM_X4(bf, kb);
            mma16816h(c[2*np],   af, bf + 0);
            mma16816h(c[2*np+1], af, bf + 2);
            kb += 16 * AROWB;
        }
    }
    __syncthreads();
#pragma unroll
    for (int it = 0; it < 8; it++) {
        int row = wid * 8 + it;
        int n = n0 + row;
        float4 v = make_float4(0.f, 0.f, 0.f, 0.f);
        if (n < N) v = *((const float4*)g_agg + (size_t)n * 32 + lane);
        __half2 h01 = __floats2half2_rn(v.x, v.y);
        __half2 h23 = __floats2half2_rn(v.z, v.w);
        uint2 u; u.x = *(uint32_t*)&h01; u.y = *(uint32_t*)&h23;
        *(uint2*)(smem + NK_A + row * AROWB + lane * 8) = u;
    }
    __syncthreads();
    // layer 1, k-half 1 (A = agg)
#pragma unroll
    for (int ks = 0; ks < 8; ks++) {
        uint32_t af[4];
        LDSM_X4(af, aBase + ks * 32);
        uint32_t kb = bBase0 + (NK_B1 - NK_B0) + ks * 32;
#pragma unroll
        for (int np = 0; np < 4; np++) {
            uint32_t bf[4];
            LDSM_X4(bf, kb);
            mma16816h(c[2*np],   af, bf + 0);
            mma16816h(c[2*np+1], af, bf + 2);
            kb += 16 * AROWB;
        }
    }
    __syncthreads();
    // t1 = silu(c + nb1) -> fp16 into NK_A; Bn2 -> NK_B0
    {
        int rA = mw * 16 + gid;
        int rB = rA + 8;
#pragma unroll
        for (int nt = 0; nt < 8; nt++) {
            int col = nw * 64 + nt * 8 + tig * 2;
            float b0 = s_nb1[col], b1 = s_nb1[col + 1];
            float2 vA = h2f2(c[nt][0]);
            float2 vB = h2f2(c[nt][1]);
            *(__half2*)(smem + NK_A + rA * AROWB + col * 2) =
                __floats2half2_rn(silu_f(vA.x + b0), silu_f(vA.y + b1));
            *(__half2*)(smem + NK_A + rB * AROWB + col * 2) =
                __floats2half2_rn(silu_f(vB.x + b0), silu_f(vB.y + b1));
        }
    }
    for (int i = tid; i < 128 * 16; i += 512) {
        int rw = i >> 4, cc = i & 15;
        *(uint4*)(smem + NK_B0 + rw * AROWB + cc * 16) = ((const uint4*)g_Bn2)[rw * 16 + cc];
    }
    __syncthreads();

    // layer 2
#pragma unroll
    for (int nt = 0; nt < 8; nt++) { c[nt][0] = 0u; c[nt][1] = 0u; }
#pragma unroll
    for (int ks = 0; ks < 8; ks++) {
        uint32_t af[4];
        LDSM_X4(af, aBase + ks * 32);
        uint32_t kb = bBase0 + ks * 32;
#pragma unroll
        for (int np = 0; np < 4; np++) {
            uint32_t bf[4];
            LDSM_X4(bf, kb);
            mma16816h(c[2*np],   af, bf + 0);
            mma16816h(c[2*np+1], af, bf + 2);
            kb += 16 * AROWB;
        }
    }
    __syncthreads();
    // stage o = c + nb2 + h (residual) fp32 into NK_O (pitch 132)
    {
        float* s_o = (float*)(smem + NK_O);
        int rA = mw * 16 + gid;
        int rB = rA + 8;
        int nA = n0 + rA, nB = n0 + rB;
#pragma unroll
        for (int nt = 0; nt < 8; nt++) {
            int col = nw * 64 + nt * 8 + tig * 2;
            float b0 = s_nb2[col], b1 = s_nb2[col + 1];
            float2 hA = make_float2(0.f, 0.f), hB = make_float2(0.f, 0.f);
            if (nA < N) hA = *(const float2*)(h + (size_t)nA * 128 + col);
            if (nB < N) hB = *(const float2*)(h + (size_t)nB * 128 + col);
            float2 vA = h2f2(c[nt][0]);
            float2 vB = h2f2(c[nt][1]);
            *(float2*)(s_o + rA * 132 + col) =
                make_float2(vA.x + b0 + hA.x, vA.y + b1 + hA.y);
            *(float2*)(s_o + rB * 132 + col) =
                make_float2(vB.x + b0 + hB.x, vB.y + b1 + hB.y);
        }
    }
    __syncthreads();
    // LayerNorm per row, write out
    {
        float* s_o = (float*)(smem + NK_O);
#pragma unroll
        for (int it = 0; it < 8; it++) {
            int row = wid * 8 + it;
            int n = n0 + row;
            float4 o = *(const float4*)(s_o + row * 132 + lane * 4);
            float s = o.x + o.y + o.z + o.w;
#pragma unroll
            for (int off = 16; off > 0; off >>= 1)
                s += __shfl_xor_sync(0xffffffffu, s, off);
            float mean = s * (1.f / 128.f);
            float dx = o.x - mean, dy = o.y - mean, dz = o.z - mean, dw = o.w - mean;
            float q = dx * dx + dy * dy + dz * dz + dw * dw;
#pragma unroll
            for (int off = 16; off > 0; off >>= 1)
                q += __shfl_xor_sync(0xffffffffu, q, off);
            float inv = rsqrtf(q * (1.f / 128.f) + 1e-5f);
            float4 g4 = *(const float4*)(s_lng + lane * 4);
            float4 bb = *(const float4*)(s_lnb + lane * 4);
            float4 y;
            y.x = dx * inv * g4.x + bb.x;
            y.y = dy * inv * g4.y + bb.y;
            y.z = dz * inv * g4.z + bb.z;
            y.w = dw * inv * g4.w + bb.w;
            if (n < N) ((float4*)out)[(size_t)n * 32 + lane] = y;
        }
    }
}

// ---------------- launcher ----------------------------------------------------
extern "C" void kernel_launch(void* const* d_in, const int* in_sizes, int n_in,
                              void* d_out, int out_size)
{
    const float* h   = (const float*)d_in[0];
    const float* x   = (const float*)d_in[1];
    const void*  ei  = d_in[2];
    const float* ea  = (const float*)d_in[3];
    const float* ew1 = (const float*)d_in[4];
    const float* eb1 = (const float*)d_in[5];
    const float* ew2 = (const float*)d_in[6];
    const float* eb2 = (const float*)d_in[7];
    const float* nw1 = (const float*)d_in[8];
    const float* nb1 = (const float*)d_in[9];
    const float* nw2 = (const float*)d_in[10];
    const float* nb2 = (const float*)d_in[11];
    const float* cw1 = (const float*)d_in[12];
    const float* cb1 = (const float*)d_in[13];
    const float* cw2 = (const float*)d_in[14];
    const float* cb2 = (const float*)d_in[15];
    const float* lgt = (const float*)d_in[16];
    const float* lng = (const float*)d_in[17];
    const float* lnb = (const float*)d_in[18];

    const int N = in_sizes[0] / 128;
    const int E = in_sizes[3] / 4;

    float* out_h = (float*)d_out;
    float* out_x = out_h + (size_t)N * 128;

    cudaFuncSetAttribute(proj_hmma, cudaFuncAttributeMaxDynamicSharedMemorySize,
                         PROJ_SMEM_BYTES);
    cudaFuncSetAttribute(edge_tc_kernel, cudaFuncAttributeMaxDynamicSharedMemorySize,
                         EDGE_SMEM_BYTES);
    cudaFuncSetAttribute(node_hmma, cudaFuncAttributeMaxDynamicSharedMemorySize,
                         NODE_SMEM_BYTES);

    setup_kernel<<<(N * 32 + 511) / 512, 512>>>(
        (const unsigned int*)ei, cw2, cb2, ew2, ew1, nw1, nw2, N);
    proj_hmma<<<(N + 127) / 128, 512, PROJ_SMEM_BYTES>>>(h, eb1, N);
    edge_tc_kernel<<<(E + 127) / 128, 512, EDGE_SMEM_BYTES>>>(
        x, ei, ea, ew1, eb2, cw1, cb1, cw2, cb2, E);
    node_hmma<<<(N + 127) / 128, 512, NODE_SMEM_BYTES>>>(
        h, x, nb1, nb2, lng, lnb, lgt, out_h, out_x, N);
}